// round 11
// baseline (speedup 1.0000x reference)
#include <cuda_runtime.h>
#include <cuda_bf16.h>
#include <math.h>
#include <stdint.h>

#define BB     4
#define LL     1024
#define DM     512
#define DI     1024
#define DS     64
#define NH     16
#define HD     64
#define CDIM   1152
#define DPROJ  2192
#define NROWS  (BB*LL)
#define TROWS  (BB*DM)
#define IT     2816
#define IM     1536
#define EPSV   1e-5f
#define NCHUNK 16

// ---- fp32 scratch ----
__device__ float g_zx  [(size_t)NROWS*DPROJ];
__device__ float g_dt  [(size_t)NROWS*NH];
__device__ float g_ldA [(size_t)NROWS*NH];
__device__ float g_xbc [(size_t)NROWS*CDIM];
__device__ float g_y   [(size_t)NROWS*DI];
__device__ float g_mo  [(size_t)NROWS*DM];
__device__ float g_hT  [(size_t)TROWS*LL];
__device__ float g_t1  [(size_t)TROWS*2*IT];
__device__ float g_t2  [(size_t)TROWS*LL];
__device__ float g_h2  [(size_t)NROWS*DM];
__device__ float g_m1  [(size_t)NROWS*2*IM];
__device__ float g_m2  [(size_t)NROWS*DM];
__device__ float g_S   [(size_t)BB*NH*NCHUNK*HD*DS];
__device__ float g_Sin [(size_t)BB*NH*NCHUNK*HD*DS];
__device__ float g_cl  [(size_t)BB*NH*NCHUNK*64];
// ---- bf16 split scratch (K'=3K) ----
__device__ __nv_bfloat16 g_ub   [(size_t)NROWS*3*DM];
__device__ __nv_bfloat16 g_gnb  [(size_t)NROWS*3*DI];
__device__ __nv_bfloat16 g_hTb  [(size_t)TROWS*3*LL];
__device__ __nv_bfloat16 g_tactb[(size_t)TROWS*3*IT];
__device__ __nv_bfloat16 g_h2b  [(size_t)NROWS*3*DM];
__device__ __nv_bfloat16 g_mactb[(size_t)NROWS*3*IM];
__device__ __nv_bfloat16 g_wip  [(size_t)2304*3*DM];
__device__ __nv_bfloat16 g_wop  [(size_t)DM*3*DI];
__device__ __nv_bfloat16 g_wgt  [(size_t)2*IT*3*LL];
__device__ __nv_bfloat16 g_wdt  [(size_t)LL*3*IT];
__device__ __nv_bfloat16 g_wgm  [(size_t)2*IM*3*DM];
__device__ __nv_bfloat16 g_wdm  [(size_t)DM*3*IM];

// ======== PTX helpers (baseline ISA, legal on compute_103) ========
__device__ __forceinline__ uint32_t smem_u32(const void* p) {
    uint32_t a;
    asm("{ .reg .u64 t; cvta.to.shared.u64 t, %1; cvt.u32.u64 %0, t; }" : "=r"(a) : "l"(p));
    return a;
}
__device__ __forceinline__ void cp16(uint32_t dst, const void* src) {
    asm volatile("cp.async.cg.shared.global [%0], [%1], 16;" :: "r"(dst), "l"(src));
}
__device__ __forceinline__ void ldsm4(uint32_t* r, uint32_t addr) {
    asm volatile("ldmatrix.sync.aligned.m8n8.x4.shared.b16 {%0,%1,%2,%3}, [%4];"
        : "=r"(r[0]), "=r"(r[1]), "=r"(r[2]), "=r"(r[3]) : "r"(addr));
}
__device__ __forceinline__ void mma16816(float* c, const uint32_t* a, const uint32_t* b) {
    asm volatile("mma.sync.aligned.m16n8k16.row.col.f32.bf16.bf16.f32 "
        "{%0,%1,%2,%3}, {%4,%5,%6,%7}, {%8,%9}, {%0,%1,%2,%3};"
        : "+f"(c[0]), "+f"(c[1]), "+f"(c[2]), "+f"(c[3])
        : "r"(a[0]), "r"(a[1]), "r"(a[2]), "r"(a[3]), "r"(b[0]), "r"(b[1]));
}

// ======== HMMA GEMM v1: 128x128x32 (used for N=512 GEMMs) ========
#define ASTRIDE 40
#define ATILE   (128*ASTRIDE*2)
#define STAGEB  (2*ATILE)

__global__ __launch_bounds__(256, 2) void gemm_tc(
    const __nv_bfloat16* __restrict__ A, const __nv_bfloat16* __restrict__ W,
    float* __restrict__ C, int M, int N, int Kp)
{
    __shared__ __align__(16) char smem[2*STAGEB];
    const int tid = threadIdx.x;
    const int m0 = blockIdx.y * 128, n0 = blockIdx.x * 128;
    const uint32_t sbase = smem_u32(smem);
    const int lane = tid & 31, warp = tid >> 5;
    const int wm = warp >> 2, wn = warp & 3;

    const int rA = tid >> 2;
    const int cByte = (tid & 3) * 16;
    const __nv_bfloat16* pA = A + (size_t)(m0 + rA) * Kp + (tid & 3) * 8;
    const __nv_bfloat16* pB = W + (size_t)(n0 + rA) * Kp + (tid & 3) * 8;
    const uint32_t dA0 = sbase + rA * 80 + cByte;
    const uint32_t dB0 = dA0 + ATILE;

    const int g = lane >> 3, r = lane & 7;
    const uint32_t aAddr = sbase + (uint32_t)(((wm*64 + (g&1)*8 + r) * ASTRIDE + (g>>1)*8) * 2);
    const uint32_t bAddr = sbase + ATILE + (uint32_t)(((wn*32 + (g>>1)*8 + r) * ASTRIDE + (g&1)*8) * 2);

    float acc[4][4][4];
#pragma unroll
    for (int i = 0; i < 4; i++)
#pragma unroll
        for (int j = 0; j < 4; j++)
#pragma unroll
            for (int k = 0; k < 4; k++) acc[i][j][k] = 0.f;

    const int KT = Kp >> 5;
    cp16(dA0, pA);            cp16(dA0 + 64*80, pA + (size_t)64 * Kp);
    cp16(dB0, pB);            cp16(dB0 + 64*80, pB + (size_t)64 * Kp);
    asm volatile("cp.async.commit_group;");

    for (int kt = 0; kt < KT; kt++) {
        if (kt + 1 < KT) {
            const __nv_bfloat16* qA = pA + (size_t)(kt + 1) * 32;
            const __nv_bfloat16* qB = pB + (size_t)(kt + 1) * 32;
            const uint32_t so = ((kt + 1) & 1) * STAGEB;
            cp16(dA0 + so, qA);            cp16(dA0 + so + 64*80, qA + (size_t)64 * Kp);
            cp16(dB0 + so, qB);            cp16(dB0 + so + 64*80, qB + (size_t)64 * Kp);
            asm volatile("cp.async.commit_group;");
            asm volatile("cp.async.wait_group 1;");
        } else {
            asm volatile("cp.async.wait_group 0;");
        }
        __syncthreads();
        const uint32_t so = (kt & 1) * STAGEB;
#pragma unroll
        for (int ks = 0; ks < 2; ks++) {
            uint32_t a[4][4], b[2][4];
#pragma unroll
            for (int mf = 0; mf < 4; mf++) ldsm4(a[mf], aAddr + so + mf*1280 + ks*32);
#pragma unroll
            for (int jp = 0; jp < 2; jp++) ldsm4(b[jp], bAddr + so + jp*1280 + ks*32);
#pragma unroll
            for (int mf = 0; mf < 4; mf++)
#pragma unroll
                for (int nf = 0; nf < 4; nf++)
                    mma16816(acc[mf][nf], a[mf], &b[nf >> 1][(nf & 1) * 2]);
        }
        __syncthreads();
    }

    const int crow = lane >> 2, ccol = (lane & 3) * 2;
#pragma unroll
    for (int mf = 0; mf < 4; mf++) {
        const int row = m0 + wm*64 + mf*16 + crow;
#pragma unroll
        for (int nf = 0; nf < 4; nf++) {
            const int col = n0 + wn*32 + nf*8 + ccol;
            if (col < N) {
                float2 v0 = make_float2(acc[mf][nf][0], acc[mf][nf][1]);
                float2 v1 = make_float2(acc[mf][nf][2], acc[mf][nf][3]);
                *(float2*)&C[(size_t)row * N + col]       = v0;
                *(float2*)&C[(size_t)(row + 8) * N + col] = v1;
            }
        }
    }
}

// ======== HMMA GEMM v2: 128x256x32, 3-stage pipeline. Weight rows padded to 256-mult. ========
#define T2_ASZ (128*80)
#define T2_BSZ (256*80)
#define T2_STG (T2_ASZ + T2_BSZ)
#define T2_SMEM (3*T2_STG)

__global__ __launch_bounds__(256, 1) void gemm_tc2(
    const __nv_bfloat16* __restrict__ A, const __nv_bfloat16* __restrict__ W,
    float* __restrict__ C, int M, int N, int Kp)
{
    extern __shared__ __align__(16) char smem2[];
    const int tid = threadIdx.x;
    const int m0 = blockIdx.y * 128, n0 = blockIdx.x * 256;
    const uint32_t sbase = smem_u32(smem2);
    const int lane = tid & 31, warp = tid >> 5;
    const int wm = warp >> 2, wn = warp & 3;      // warp tile 64x64

    const int lrow = tid >> 2;
    const int cq = tid & 3;
    const __nv_bfloat16* pA = A + (size_t)(m0 + lrow) * Kp + cq * 8;
    const __nv_bfloat16* pB = W + (size_t)(n0 + lrow) * Kp + cq * 8;
    const uint32_t dA = sbase + lrow * 80 + cq * 16;
    const uint32_t dB = sbase + T2_ASZ + lrow * 80 + cq * 16;

    const int g = lane >> 3, r = lane & 7;
    const uint32_t aAddr = sbase + (uint32_t)(((wm*64 + (g&1)*8 + r) * 40 + (g>>1)*8) * 2);
    const uint32_t bAddr = sbase + T2_ASZ + (uint32_t)(((wn*64 + (g>>1)*8 + r) * 40 + (g&1)*8) * 2);

    float acc[4][8][4];
#pragma unroll
    for (int i = 0; i < 4; i++)
#pragma unroll
        for (int j = 0; j < 8; j++)
#pragma unroll
            for (int k = 0; k < 4; k++) acc[i][j][k] = 0.f;

    const int KT = Kp >> 5;

#define T2_LOAD(kt) do { \
    const uint32_t _so = ((kt) % 3) * T2_STG; \
    const size_t _ko = (size_t)(kt) * 32; \
    cp16(dA + _so, pA + _ko); \
    cp16(dA + _so + 64*80, pA + _ko + (size_t)64 * Kp); \
    cp16(dB + _so,          pB + _ko); \
    cp16(dB + _so + 64*80,  pB + _ko + (size_t)64 * Kp); \
    cp16(dB + _so + 128*80, pB + _ko + (size_t)128 * Kp); \
    cp16(dB + _so + 192*80, pB + _ko + (size_t)192 * Kp); \
    asm volatile("cp.async.commit_group;"); \
} while (0)

    T2_LOAD(0);
    T2_LOAD(1);

    for (int kt = 0; kt < KT; kt++) {
        asm volatile("cp.async.wait_group 1;");
        __syncthreads();
        if (kt + 2 < KT) { T2_LOAD(kt + 2); }
        else { asm volatile("cp.async.commit_group;"); }
        const uint32_t so = (kt % 3) * T2_STG;
#pragma unroll
        for (int ks = 0; ks < 2; ks++) {
            uint32_t a[4][4], b[4][4];
#pragma unroll
            for (int mf = 0; mf < 4; mf++) ldsm4(a[mf], aAddr + so + mf*1280 + ks*32);
#pragma unroll
            for (int np = 0; np < 4; np++) ldsm4(b[np], bAddr + so + np*1280 + ks*32);
#pragma unroll
            for (int mf = 0; mf < 4; mf++)
#pragma unroll
                for (int nf = 0; nf < 8; nf++)
                    mma16816(acc[mf][nf], a[mf], &b[nf >> 1][(nf & 1) * 2]);
        }
    }
#undef T2_LOAD

    // epilogue WITH col<N guard (in-proj has N=2192, grid covers 2304)
    const int crow = lane >> 2, ccol = (lane & 3) * 2;
#pragma unroll
    for (int mf = 0; mf < 4; mf++) {
        const int row = m0 + wm*64 + mf*16 + crow;
#pragma unroll
        for (int nf = 0; nf < 8; nf++) {
            const int col = n0 + wn*64 + nf*8 + ccol;
            if (col < N) {
                float2 v0 = make_float2(acc[mf][nf][0], acc[mf][nf][1]);
                float2 v1 = make_float2(acc[mf][nf][2], acc[mf][nf][3]);
                *(float2*)&C[(size_t)row * N + col]       = v0;
                *(float2*)&C[(size_t)(row + 8) * N + col] = v1;
            }
        }
    }
}

// ======== bf16 splits ========
__device__ __forceinline__ void split3_act(__nv_bfloat16* dst, size_t rb, int K, int k, float v) {
    __nv_bfloat16 hi = __float2bfloat16(v);
    __nv_bfloat16 lo = __float2bfloat16(v - __bfloat162float(hi));
    dst[rb + k] = hi; dst[rb + K + k] = lo; dst[rb + 2*K + k] = hi;
}
__global__ __launch_bounds__(256) void split_act(const float* __restrict__ src,
    __nv_bfloat16* __restrict__ dst, int rows, int K)
{
    int i = blockIdx.x * 256 + threadIdx.x;
    if (i >= rows * K) return;
    int r = i / K, k = i - r * K;
    split3_act(dst, (size_t)r * 3 * K, K, k, src[i]);
}
__global__ __launch_bounds__(256) void split_wt(const float* __restrict__ src,
    __nv_bfloat16* __restrict__ dst, int N, int Npad, int K)
{
    int i = blockIdx.x * 256 + threadIdx.x;
    if (i >= Npad * K) return;
    int r = i / K, k = i - r * K;
    float v = (r < N) ? src[(size_t)r * K + k] : 0.f;
    __nv_bfloat16 hi = __float2bfloat16(v);
    __nv_bfloat16 lo = __float2bfloat16(v - __bfloat162float(hi));
    size_t b = (size_t)r * 3 * K;
    dst[b + k] = hi; dst[b + K + k] = hi; dst[b + 2*K + k] = lo;
}

// ======== Mamba pointwise ========
__global__ __launch_bounds__(256) void dt_kernel(const float* __restrict__ dt_bias, const float* __restrict__ A_log)
{
    int idx = blockIdx.x * 256 + threadIdx.x;
    int h = idx & 15, r = idx >> 4;
    float v = g_zx[(size_t)r * DPROJ + (DPROJ - NH) + h] + dt_bias[h];
    float dt = (v > 20.f) ? v : log1pf(expf(v));
    g_dt[idx] = dt;
    g_ldA[idx] = -dt * expf(A_log[h]);
}
__global__ __launch_bounds__(256) void conv_kernel(const float* __restrict__ cw, const float* __restrict__ cb)
{
    int idx = blockIdx.x * 256 + threadIdx.x;
    if (idx >= NROWS * CDIM) return;
    int c = idx % CDIM, r = idx / CDIM, l = r & (LL - 1);
    float acc = cb[c];
#pragma unroll
    for (int i = 0; i < 4; i++) {
        int li = l - 3 + i;
        if (li >= 0) acc += g_zx[(size_t)(r - 3 + i) * DPROJ + DI + c] * cw[c * 4 + i];
    }
    g_xbc[idx] = acc / (1.f + expf(-acc));
}

// ======== chunked scan ========
__device__ __forceinline__ float dot4f(float4 a, float4 b) { return a.x*b.x + a.y*b.y + a.z*b.z + a.w*b.w; }

__global__ __launch_bounds__(256) void scan_chunk(const float* __restrict__ Dv)
{
    extern __shared__ float sm[];
    float* sX  = sm;
    float* sB  = sm + 64*68;
    float* sCG = sm + 2*64*68;
    float* sdt = sm + 3*64*68;
    float* sL  = sdt + 64;
    float* sW  = sL + 64;
    const int bhc = blockIdx.x;
    const int bh = bhc >> 4, c = bhc & 15;
    const int b = bh >> 4, h = bh & 15;
    const int tid = threadIdx.x;
    const size_t row0 = (size_t)b * LL + c * 64;

    for (int i = tid; i < 64*64; i += 256) {
        int t = i >> 6, n = i & 63;
        size_t rb = (row0 + t) * CDIM;
        sX[t*68+n]  = g_xbc[rb + h*64 + n];
        sB[t*68+n]  = g_xbc[rb + DI + n];
        sCG[t*68+n] = g_xbc[rb + DI + DS + n];
    }
    if (tid < 64) {
        size_t rr = (row0 + tid) * NH + h;
        sdt[tid] = g_dt[rr]; sL[tid] = g_ldA[rr];
    }
    __syncthreads();
    if (tid == 0) { float a = 0.f; for (int t = 0; t < 64; t++) { a += sL[t]; sL[t] = a; } }
    __syncthreads();
    if (tid < 64) {
        sW[tid] = __expf(sL[63] - sL[tid]) * sdt[tid];
        g_cl[(size_t)bhc * 64 + tid] = sL[tid];
    }
    __syncthreads();

    const int ty = tid >> 4, tx = tid & 15;
    float acc[4][4];
#pragma unroll
    for (int i = 0; i < 4; i++)
#pragma unroll
        for (int j = 0; j < 4; j++) acc[i][j] = 0.f;
    for (int n = 0; n < 64; n += 4) {
        float4 cv[4], bv[4];
#pragma unroll
        for (int i = 0; i < 4; i++) cv[i] = *(const float4*)&sCG[(ty*4+i)*68 + n];
#pragma unroll
        for (int j = 0; j < 4; j++) bv[j] = *(const float4*)&sB[(tx*4+j)*68 + n];
#pragma unroll
        for (int i = 0; i < 4; i++)
#pragma unroll
            for (int j = 0; j < 4; j++) acc[i][j] += dot4f(cv[i], bv[j]);
    }
    __syncthreads();
#pragma unroll
    for (int i = 0; i < 4; i++) {
        int t = ty*4 + i; float lt = sL[t];
#pragma unroll
        for (int j = 0; j < 4; j++) {
            int tau = tx*4 + j;
            sCG[t*68+tau] = (tau <= t) ? __expf(lt - sL[tau]) * sdt[tau] * acc[i][j] : 0.f;
        }
    }
    __syncthreads();

    float acc2[4][4];
#pragma unroll
    for (int i = 0; i < 4; i++)
#pragma unroll
        for (int j = 0; j < 4; j++) acc2[i][j] = 0.f;
    for (int tau = 0; tau < 64; tau += 4) {
        float xr[4][4];
#pragma unroll
        for (int s = 0; s < 4; s++) *(float4*)xr[s] = *(const float4*)&sX[(tau+s)*68 + tx*4];
#pragma unroll
        for (int i = 0; i < 4; i++) {
            float gr[4];
            *(float4*)gr = *(const float4*)&sCG[(ty*4+i)*68 + tau];
#pragma unroll
            for (int j = 0; j < 4; j++)
                acc2[i][j] += gr[0]*xr[0][j] + gr[1]*xr[1][j] + gr[2]*xr[2][j] + gr[3]*xr[3][j];
        }
    }
    const float Dh = Dv[h];
#pragma unroll
    for (int i = 0; i < 4; i++) {
        int t = ty*4 + i;
#pragma unroll
        for (int j = 0; j < 4; j++) {
            int p = tx*4 + j;
            g_y[(row0 + t) * DI + h*64 + p] = acc2[i][j] + Dh * sX[t*68+p];
        }
    }

    float acc3[4][4];
#pragma unroll
    for (int i = 0; i < 4; i++)
#pragma unroll
        for (int j = 0; j < 4; j++) acc3[i][j] = 0.f;
    for (int tau = 0; tau < 64; tau++) {
        float w = sW[tau];
        float xp[4], bn[4];
        *(float4*)xp = *(const float4*)&sX[tau*68 + ty*4];
        *(float4*)bn = *(const float4*)&sB[tau*68 + tx*4];
#pragma unroll
        for (int i = 0; i < 4; i++) {
            float xw = w * xp[i];
#pragma unroll
            for (int j = 0; j < 4; j++) acc3[i][j] += xw * bn[j];
        }
    }
#pragma unroll
    for (int i = 0; i < 4; i++)
#pragma unroll
        for (int j = 0; j < 4; j++)
            g_S[(size_t)bhc * 4096 + (ty*4+i) * 64 + (tx*4+j)] = acc3[i][j];
}

__global__ __launch_bounds__(256) void scan_seq()
{
    const int bh = blockIdx.x;
    const int tid = threadIdx.x;
    float s[16];
#pragma unroll
    for (int i = 0; i < 16; i++) s[i] = 0.f;
    const size_t base = (size_t)bh * NCHUNK * 4096;
    for (int c = 0; c < NCHUNK; c++) {
        float P = __expf(g_cl[((size_t)bh * NCHUNK + c) * 64 + 63]);
        size_t off = base + (size_t)c * 4096 + (size_t)tid * 16;
#pragma unroll
        for (int i = 0; i < 16; i += 4) {
            float4 Sv = *(const float4*)&g_S[off + i];
            *(float4*)&g_Sin[off + i] = make_float4(s[i], s[i+1], s[i+2], s[i+3]);
            s[i]   = s[i]  *P + Sv.x; s[i+1] = s[i+1]*P + Sv.y;
            s[i+2] = s[i+2]*P + Sv.z; s[i+3] = s[i+3]*P + Sv.w;
        }
    }
}

__global__ __launch_bounds__(256) void scan_inter()
{
    __shared__ float sC[64*68];
    __shared__ float sS[64*68];
    __shared__ float sE[64];
    const int bhc = blockIdx.x;
    const int bh = bhc >> 4, c = bhc & 15;
    const int b = bh >> 4, h = bh & 15;
    const int tid = threadIdx.x;
    const size_t row0 = (size_t)b * LL + c * 64;

    for (int i = tid; i < 64*64; i += 256) {
        int t = i >> 6, n = i & 63;
        sC[t*68+n] = g_xbc[(row0 + t) * CDIM + DI + DS + n];
        sS[t*68+n] = g_Sin[(size_t)bhc * 4096 + t * 64 + n];
    }
    if (tid < 64) sE[tid] = __expf(g_cl[(size_t)bhc * 64 + tid]);
    __syncthreads();

    const int ty = tid >> 4, tx = tid & 15;
    float acc[4][4];
#pragma unroll
    for (int i = 0; i < 4; i++)
#pragma unroll
        for (int j = 0; j < 4; j++) acc[i][j] = 0.f;
    for (int n = 0; n < 64; n += 4) {
        float4 cv[4], sv[4];
#pragma unroll
        for (int i = 0; i < 4; i++) cv[i] = *(const float4*)&sC[(ty*4+i)*68 + n];
#pragma unroll
        for (int j = 0; j < 4; j++) sv[j] = *(const float4*)&sS[(tx*4+j)*68 + n];
#pragma unroll
        for (int i = 0; i < 4; i++)
#pragma unroll
            for (int j = 0; j < 4; j++) acc[i][j] += dot4f(cv[i], sv[j]);
    }
#pragma unroll
    for (int i = 0; i < 4; i++) {
        int t = ty*4 + i; float e = sE[t];
#pragma unroll
        for (int j = 0; j < 4; j++) {
            size_t ix = (row0 + t) * DI + h*64 + tx*4 + j;
            g_y[ix] += e * acc[i][j];
        }
    }
}

// ======== norms / gating ========
__device__ __forceinline__ float block_reduce_sum(float v, float* red)
{
#pragma unroll
    for (int o = 16; o; o >>= 1) v += __shfl_xor_sync(0xffffffffu, v, o);
    if ((threadIdx.x & 31) == 0) red[threadIdx.x >> 5] = v;
    __syncthreads();
    float t = 0.f;
#pragma unroll
    for (int i = 0; i < 8; i++) t += red[i];
    return t;
}

__global__ __launch_bounds__(256) void gate_norm_kernel(const float* __restrict__ norm_w)
{
    __shared__ float red[8];
    int r = blockIdx.x;
    const float* zrow = g_zx + (size_t)r * DPROJ;
    const float* yrow = g_y + (size_t)r * DI;
    float vals[4]; float ss = 0.f;
#pragma unroll
    for (int i = 0; i < 4; i++) {
        int c = threadIdx.x + i*256;
        float z = zrow[c];
        float g = yrow[c] * (z / (1.f + expf(-z)));
        vals[i] = g; ss += g*g;
    }
    float sc = rsqrtf(block_reduce_sum(ss, red) * (1.f/1024.f) + EPSV);
    size_t rb = (size_t)r * 3 * DI;
#pragma unroll
    for (int i = 0; i < 4; i++) {
        int c = threadIdx.x + i*256;
        split3_act(g_gnb, rb, DI, c, vals[i] * sc * norm_w[c]);
    }
}

__global__ __launch_bounds__(256) void add_rms_hT_kernel(const float* __restrict__ u)
{
    __shared__ float red[8];
    int r = blockIdx.x;
    int b = r >> 10, l = r & (LL - 1);
    const float* ur = u + (size_t)r * DM;
    const float* mr = g_mo + (size_t)r * DM;
    float vals[2]; float ss = 0.f;
#pragma unroll
    for (int i = 0; i < 2; i++) {
        int d = threadIdx.x + i*256;
        float v = ur[d] + mr[d];
        vals[i] = v; ss += v*v;
    }
    float sc = rsqrtf(block_reduce_sum(ss, red) * (1.f/512.f) + EPSV);
#pragma unroll
    for (int i = 0; i < 2; i++) {
        int d = threadIdx.x + i*256;
        g_hT[(size_t)(b*DM + d) * LL + l] = vals[i] * sc;
    }
}

__global__ __launch_bounds__(256) void glu_kernel(const float* __restrict__ t,
    __nv_bfloat16* __restrict__ o, int half, int total)
{
    int idx = blockIdx.x * 256 + threadIdx.x;
    if (idx >= total) return;
    int r = idx / half, j = idx - r*half;
    const float* row = t + (size_t)r * 2 * half;
    float g = row[j], up = row[half + j];
    split3_act(o, (size_t)r * 3 * half, half, j, (g / (1.f + expf(-g))) * up);
}

__global__ __launch_bounds__(256) void add_rms_x2_kernel()
{
    __shared__ float red[8];
    int r = blockIdx.x;
    int b = r >> 9, d = r & (DM - 1);
    const float* hr = g_hT + (size_t)r * LL;
    const float* tr = g_t2 + (size_t)r * LL;
    float vals[4]; float ss = 0.f;
#pragma unroll
    for (int i = 0; i < 4; i++) {
        int l = threadIdx.x + i*256;
        float v = hr[l] + tr[l];
        vals[i] = v; ss += v*v;
    }
    float sc = rsqrtf(block_reduce_sum(ss, red) * (1.f/1024.f) + EPSV);
#pragma unroll
    for (int i = 0; i < 4; i++) {
        int l = threadIdx.x + i*256;
        g_h2[(size_t)(b*LL + l) * DM + d] = vals[i] * sc;
    }
}

__global__ __launch_bounds__(256) void final_rms_kernel(float* __restrict__ out)
{
    __shared__ float red[8];
    int r = blockIdx.x;
    const float* hr = g_h2 + (size_t)r * DM;
    const float* mr = g_m2 + (size_t)r * DM;
    float vals[2]; float ss = 0.f;
#pragma unroll
    for (int i = 0; i < 2; i++) {
        int d = threadIdx.x + i*256;
        float v = hr[d] + mr[d];
        vals[i] = v; ss += v*v;
    }
    float sc = rsqrtf(block_reduce_sum(ss, red) * (1.f/512.f) + EPSV);
#pragma unroll
    for (int i = 0; i < 2; i++) {
        int d = threadIdx.x + i*256;
        out[(size_t)r * DM + d] = vals[i] * sc;
    }
}

// ======== launch ========
#define GETSYM(p, s) cudaGetSymbolAddress((void**)&p, s)
extern "C" void kernel_launch(void* const* d_in, const int* in_sizes, int n_in,
                              void* d_out, int out_size)
{
    const float* u          = (const float*)d_in[0];
    const float* in_proj_w  = (const float*)d_in[1];
    const float* conv_w     = (const float*)d_in[2];
    const float* conv_b     = (const float*)d_in[3];
    const float* dt_bias    = (const float*)d_in[4];
    const float* A_log      = (const float*)d_in[5];
    const float* Dv         = (const float*)d_in[6];
    const float* norm_w     = (const float*)d_in[7];
    const float* out_proj_w = (const float*)d_in[8];
    const float* gu_t       = (const float*)d_in[9];
    const float* down_t     = (const float*)d_in[10];
    const float* gu_m       = (const float*)d_in[11];
    const float* down_m     = (const float*)d_in[12];
    float* out = (float*)d_out;

    float *zx, *mo, *hT, *t1, *t2, *h2, *m1, *m2;
    __nv_bfloat16 *ub, *gnb, *hTb, *tactb, *h2b, *mactb, *wip, *wop, *wgt, *wdt, *wgm, *wdm;
    GETSYM(zx, g_zx); GETSYM(mo, g_mo); GETSYM(hT, g_hT); GETSYM(t1, g_t1);
    GETSYM(t2, g_t2); GETSYM(h2, g_h2); GETSYM(m1, g_m1); GETSYM(m2, g_m2);
    GETSYM(ub, g_ub); GETSYM(gnb, g_gnb); GETSYM(hTb, g_hTb); GETSYM(tactb, g_tactb);
    GETSYM(h2b, g_h2b); GETSYM(mactb, g_mactb);
    GETSYM(wip, g_wip); GETSYM(wop, g_wop); GETSYM(wgt, g_wgt);
    GETSYM(wdt, g_wdt); GETSYM(wgm, g_wgm); GETSYM(wdm, g_wdm);

    cudaFuncSetAttribute(scan_chunk, cudaFuncAttributeMaxDynamicSharedMemorySize, 53248);
    cudaFuncSetAttribute(gemm_tc2, cudaFuncAttributeMaxDynamicSharedMemorySize, T2_SMEM);

    // weight + input splits (bf16 hi/lo, K'=3K)
    split_wt<<<(2304*512 + 255)/256, 256>>>(in_proj_w, wip, DPROJ, 2304, DM);
    split_wt<<<(512*1024 + 255)/256, 256>>>(out_proj_w, wop, DM, DM, DI);
    split_wt<<<(5632*1024 + 255)/256, 256>>>(gu_t, wgt, 2*IT, 2*IT, LL);
    split_wt<<<(1024*2816 + 255)/256, 256>>>(down_t, wdt, LL, LL, IT);
    split_wt<<<(3072*512 + 255)/256, 256>>>(gu_m, wgm, 2*IM, 2*IM, DM);
    split_wt<<<(512*1536 + 255)/256, 256>>>(down_m, wdm, DM, DM, IM);
    split_act<<<(NROWS*DM + 255)/256, 256>>>(u, ub, NROWS, DM);

    // ---- Mamba2 ----
    gemm_tc2<<<dim3(9, 32), 256, T2_SMEM>>>(ub, wip, zx, NROWS, DPROJ, 3*DM);
    dt_kernel<<<(NROWS*NH)/256, 256>>>(dt_bias, A_log);
    conv_kernel<<<(NROWS*CDIM + 255)/256, 256>>>(conv_w, conv_b);
    scan_chunk<<<BB*NH*NCHUNK, 256, 52992>>>(Dv);
    scan_seq<<<BB*NH, 256>>>();
    scan_inter<<<BB*NH*NCHUNK, 256>>>();
    gate_norm_kernel<<<NROWS, 256>>>(norm_w);
    gemm_tc<<<dim3(4, 32), 256>>>(gnb, wop, mo, NROWS, DM, 3*DI);
    add_rms_hT_kernel<<<NROWS, 256>>>(u);
    split_act<<<(TROWS*LL + 255)/256, 256>>>(hT, hTb, TROWS, LL);

    // ---- token-mixing SwiGLU ----
    gemm_tc2<<<dim3(22, 16), 256, T2_SMEM>>>(hTb, wgt, t1, TROWS, 2*IT, 3*LL);
    glu_kernel<<<(TROWS*IT + 255)/256, 256>>>(t1, tactb, IT, TROWS*IT);
    gemm_tc2<<<dim3(4, 16), 256, T2_SMEM>>>(tactb, wdt, t2, TROWS, LL, 3*IT);
    add_rms_x2_kernel<<<TROWS, 256>>>();
    split_act<<<(NROWS*DM + 255)/256, 256>>>(h2, h2b, NROWS, DM);

    // ---- channel SwiGLU ----
    gemm_tc2<<<dim3(12, 32), 256, T2_SMEM>>>(h2b, wgm, m1, NROWS, 2*IM, 3*DM);
    glu_kernel<<<(NROWS*IM + 255)/256, 256>>>(m1, mactb, IM, NROWS*IM);
    gemm_tc<<<dim3(4, 32), 256>>>(mactb, wdm, m2, NROWS, DM, 3*IM);
    final_rms_kernel<<<NROWS, 256>>>(out);
}

// round 12
// speedup vs baseline: 1.1619x; 1.1619x over previous
#include <cuda_runtime.h>
#include <cuda_bf16.h>
#include <math.h>
#include <stdint.h>

#define BB     4
#define LL     1024
#define DM     512
#define DI     1024
#define DS     64
#define NH     16
#define HD     64
#define CDIM   1152
#define DPROJ  2192
#define NROWS  (BB*LL)
#define TROWS  (BB*DM)
#define IT     2816
#define IM     1536
#define EPSV   1e-5f
#define NCHUNK 16

// ---- fp32 scratch ----
__device__ float g_zx  [(size_t)NROWS*DPROJ];
__device__ float g_dt  [(size_t)NROWS*NH];
__device__ float g_ldA [(size_t)NROWS*NH];
__device__ float g_xbc [(size_t)NROWS*CDIM];
__device__ float g_y   [(size_t)NROWS*DI];
__device__ float g_mo  [(size_t)NROWS*DM];
__device__ float g_hT  [(size_t)TROWS*LL];
__device__ float g_t1  [(size_t)TROWS*2*IT];
__device__ float g_t2  [(size_t)TROWS*LL];
__device__ float g_h2  [(size_t)NROWS*DM];
__device__ float g_m1  [(size_t)NROWS*2*IM];
__device__ float g_m2  [(size_t)NROWS*DM];
__device__ float g_S   [(size_t)BB*NH*NCHUNK*HD*DS];
__device__ float g_Sin [(size_t)BB*NH*NCHUNK*HD*DS];
__device__ float g_cl  [(size_t)BB*NH*NCHUNK*64];
// ---- bf16 split scratch (K'=3K) ----
__device__ __nv_bfloat16 g_ub   [(size_t)NROWS*3*DM];
__device__ __nv_bfloat16 g_gnb  [(size_t)NROWS*3*DI];
__device__ __nv_bfloat16 g_hTb  [(size_t)TROWS*3*LL];
__device__ __nv_bfloat16 g_tactb[(size_t)TROWS*3*IT];
__device__ __nv_bfloat16 g_h2b  [(size_t)NROWS*3*DM];
__device__ __nv_bfloat16 g_mactb[(size_t)NROWS*3*IM];
__device__ __nv_bfloat16 g_wip  [(size_t)2304*3*DM];
__device__ __nv_bfloat16 g_wop  [(size_t)DM*3*DI];
__device__ __nv_bfloat16 g_wgt  [(size_t)2*IT*3*LL];
__device__ __nv_bfloat16 g_wdt  [(size_t)LL*3*IT];
__device__ __nv_bfloat16 g_wgm  [(size_t)2*IM*3*DM];
__device__ __nv_bfloat16 g_wdm  [(size_t)DM*3*IM];

// ======== PTX helpers (baseline ISA, legal on compute_103) ========
__device__ __forceinline__ uint32_t smem_u32(const void* p) {
    uint32_t a;
    asm("{ .reg .u64 t; cvta.to.shared.u64 t, %1; cvt.u32.u64 %0, t; }" : "=r"(a) : "l"(p));
    return a;
}
__device__ __forceinline__ void cp16(uint32_t dst, const void* src) {
    asm volatile("cp.async.cg.shared.global [%0], [%1], 16;" :: "r"(dst), "l"(src));
}
__device__ __forceinline__ void ldsm4(uint32_t* r, uint32_t addr) {
    asm volatile("ldmatrix.sync.aligned.m8n8.x4.shared.b16 {%0,%1,%2,%3}, [%4];"
        : "=r"(r[0]), "=r"(r[1]), "=r"(r[2]), "=r"(r[3]) : "r"(addr));
}
__device__ __forceinline__ void mma16816(float* c, const uint32_t* a, const uint32_t* b) {
    asm volatile("mma.sync.aligned.m16n8k16.row.col.f32.bf16.bf16.f32 "
        "{%0,%1,%2,%3}, {%4,%5,%6,%7}, {%8,%9}, {%0,%1,%2,%3};"
        : "+f"(c[0]), "+f"(c[1]), "+f"(c[2]), "+f"(c[3])
        : "r"(a[0]), "r"(a[1]), "r"(a[2]), "r"(a[3]), "r"(b[0]), "r"(b[1]));
}

// ======== HMMA GEMM: 128x128x32 tile, 3-stage cp.async pipeline, occ 2 ========
#define ASTRIDE 40                 // bf16 elems per smem row (80B)
#define ATILE   (128*ASTRIDE*2)    // 10240 B
#define STAGEB  (2*ATILE)          // 20480 B per stage (A then B)
#define G_SMEM  (3*STAGEB)         // 61440 B

__global__ __launch_bounds__(256, 2) void gemm_tc(
    const __nv_bfloat16* __restrict__ A, const __nv_bfloat16* __restrict__ W,
    float* __restrict__ C, int M, int N, int Kp)
{
    extern __shared__ __align__(16) char smem[];
    const int tid = threadIdx.x;
    const int m0 = blockIdx.y * 128, n0 = blockIdx.x * 128;
    const uint32_t sbase = smem_u32(smem);
    const int lane = tid & 31, warp = tid >> 5;
    const int wm = warp >> 2, wn = warp & 3;

    const int rA = tid >> 2;                 // 0..63
    const int cByte = (tid & 3) * 16;
    const __nv_bfloat16* pA = A + (size_t)(m0 + rA) * Kp + (tid & 3) * 8;
    const __nv_bfloat16* pB = W + (size_t)(n0 + rA) * Kp + (tid & 3) * 8;
    const uint32_t dA0 = sbase + rA * 80 + cByte;
    const uint32_t dB0 = dA0 + ATILE;

    const int g = lane >> 3, r = lane & 7;
    const uint32_t aAddr = sbase + (uint32_t)(((wm*64 + (g&1)*8 + r) * ASTRIDE + (g>>1)*8) * 2);
    const uint32_t bAddr = sbase + ATILE + (uint32_t)(((wn*32 + (g>>1)*8 + r) * ASTRIDE + (g&1)*8) * 2);

    float acc[4][4][4];
#pragma unroll
    for (int i = 0; i < 4; i++)
#pragma unroll
        for (int j = 0; j < 4; j++)
#pragma unroll
            for (int k = 0; k < 4; k++) acc[i][j][k] = 0.f;

    const int KT = Kp >> 5;

#define G_LOAD(kt) do { \
    const uint32_t _so = ((kt) % 3) * STAGEB; \
    const size_t _ko = (size_t)(kt) * 32; \
    cp16(dA0 + _so, pA + _ko);          cp16(dA0 + _so + 64*80, pA + _ko + (size_t)64 * Kp); \
    cp16(dB0 + _so, pB + _ko);          cp16(dB0 + _so + 64*80, pB + _ko + (size_t)64 * Kp); \
    asm volatile("cp.async.commit_group;"); \
} while (0)

    G_LOAD(0);
    G_LOAD(1);

    for (int kt = 0; kt < KT; kt++) {
        asm volatile("cp.async.wait_group 1;");
        __syncthreads();                    // all warps done with stage (kt-1)'s slot; stage kt ready
        if (kt + 2 < KT) { G_LOAD(kt + 2); }
        else { asm volatile("cp.async.commit_group;"); }   // keep group count aligned
        const uint32_t so = (kt % 3) * STAGEB;
#pragma unroll
        for (int ks = 0; ks < 2; ks++) {
            uint32_t a[4][4], b[2][4];
#pragma unroll
            for (int mf = 0; mf < 4; mf++) ldsm4(a[mf], aAddr + so + mf*1280 + ks*32);
#pragma unroll
            for (int jp = 0; jp < 2; jp++) ldsm4(b[jp], bAddr + so + jp*1280 + ks*32);
#pragma unroll
            for (int mf = 0; mf < 4; mf++)
#pragma unroll
                for (int nf = 0; nf < 4; nf++)
                    mma16816(acc[mf][nf], a[mf], &b[nf >> 1][(nf & 1) * 2]);
        }
    }
#undef G_LOAD

    const int crow = lane >> 2, ccol = (lane & 3) * 2;
#pragma unroll
    for (int mf = 0; mf < 4; mf++) {
        const int row = m0 + wm*64 + mf*16 + crow;
#pragma unroll
        for (int nf = 0; nf < 4; nf++) {
            const int col = n0 + wn*32 + nf*8 + ccol;
            if (col < N) {
                float2 v0 = make_float2(acc[mf][nf][0], acc[mf][nf][1]);
                float2 v1 = make_float2(acc[mf][nf][2], acc[mf][nf][3]);
                *(float2*)&C[(size_t)row * N + col]       = v0;
                *(float2*)&C[(size_t)(row + 8) * N + col] = v1;
            }
        }
    }
}

// ======== bf16 splits ========
__device__ __forceinline__ void split3_act(__nv_bfloat16* dst, size_t rb, int K, int k, float v) {
    __nv_bfloat16 hi = __float2bfloat16(v);
    __nv_bfloat16 lo = __float2bfloat16(v - __bfloat162float(hi));
    dst[rb + k] = hi; dst[rb + K + k] = lo; dst[rb + 2*K + k] = hi;
}
__global__ __launch_bounds__(256) void split_act(const float* __restrict__ src,
    __nv_bfloat16* __restrict__ dst, int rows, int K)
{
    int i = blockIdx.x * 256 + threadIdx.x;
    if (i >= rows * K) return;
    int r = i / K, k = i - r * K;
    split3_act(dst, (size_t)r * 3 * K, K, k, src[i]);
}
__global__ __launch_bounds__(256) void split_wt(const float* __restrict__ src,
    __nv_bfloat16* __restrict__ dst, int N, int Npad, int K)
{
    int i = blockIdx.x * 256 + threadIdx.x;
    if (i >= Npad * K) return;
    int r = i / K, k = i - r * K;
    float v = (r < N) ? src[(size_t)r * K + k] : 0.f;
    __nv_bfloat16 hi = __float2bfloat16(v);
    __nv_bfloat16 lo = __float2bfloat16(v - __bfloat162float(hi));
    size_t b = (size_t)r * 3 * K;
    dst[b + k] = hi; dst[b + K + k] = hi; dst[b + 2*K + k] = lo;
}

// ======== Mamba pointwise ========
__global__ __launch_bounds__(256) void dt_kernel(const float* __restrict__ dt_bias, const float* __restrict__ A_log)
{
    int idx = blockIdx.x * 256 + threadIdx.x;
    int h = idx & 15, r = idx >> 4;
    float v = g_zx[(size_t)r * DPROJ + (DPROJ - NH) + h] + dt_bias[h];
    float dt = (v > 20.f) ? v : log1pf(expf(v));
    g_dt[idx] = dt;
    g_ldA[idx] = -dt * expf(A_log[h]);
}
__global__ __launch_bounds__(256) void conv_kernel(const float* __restrict__ cw, const float* __restrict__ cb)
{
    int idx = blockIdx.x * 256 + threadIdx.x;
    if (idx >= NROWS * CDIM) return;
    int c = idx % CDIM, r = idx / CDIM, l = r & (LL - 1);
    float acc = cb[c];
#pragma unroll
    for (int i = 0; i < 4; i++) {
        int li = l - 3 + i;
        if (li >= 0) acc += g_zx[(size_t)(r - 3 + i) * DPROJ + DI + c] * cw[c * 4 + i];
    }
    g_xbc[idx] = acc / (1.f + expf(-acc));
}

// ======== chunked scan ========
__device__ __forceinline__ float dot4f(float4 a, float4 b) { return a.x*b.x + a.y*b.y + a.z*b.z + a.w*b.w; }

__global__ __launch_bounds__(256) void scan_chunk(const float* __restrict__ Dv)
{
    extern __shared__ float sm[];
    float* sX  = sm;
    float* sB  = sm + 64*68;
    float* sCG = sm + 2*64*68;
    float* sdt = sm + 3*64*68;
    float* sL  = sdt + 64;
    float* sW  = sL + 64;
    const int bhc = blockIdx.x;
    const int bh = bhc >> 4, c = bhc & 15;
    const int b = bh >> 4, h = bh & 15;
    const int tid = threadIdx.x;
    const size_t row0 = (size_t)b * LL + c * 64;

    for (int i = tid; i < 64*64; i += 256) {
        int t = i >> 6, n = i & 63;
        size_t rb = (row0 + t) * CDIM;
        sX[t*68+n]  = g_xbc[rb + h*64 + n];
        sB[t*68+n]  = g_xbc[rb + DI + n];
        sCG[t*68+n] = g_xbc[rb + DI + DS + n];
    }
    if (tid < 64) {
        size_t rr = (row0 + tid) * NH + h;
        sdt[tid] = g_dt[rr]; sL[tid] = g_ldA[rr];
    }
    __syncthreads();
    if (tid == 0) { float a = 0.f; for (int t = 0; t < 64; t++) { a += sL[t]; sL[t] = a; } }
    __syncthreads();
    if (tid < 64) {
        sW[tid] = __expf(sL[63] - sL[tid]) * sdt[tid];
        g_cl[(size_t)bhc * 64 + tid] = sL[tid];
    }
    __syncthreads();

    const int ty = tid >> 4, tx = tid & 15;
    float acc[4][4];
#pragma unroll
    for (int i = 0; i < 4; i++)
#pragma unroll
        for (int j = 0; j < 4; j++) acc[i][j] = 0.f;
    for (int n = 0; n < 64; n += 4) {
        float4 cv[4], bv[4];
#pragma unroll
        for (int i = 0; i < 4; i++) cv[i] = *(const float4*)&sCG[(ty*4+i)*68 + n];
#pragma unroll
        for (int j = 0; j < 4; j++) bv[j] = *(const float4*)&sB[(tx*4+j)*68 + n];
#pragma unroll
        for (int i = 0; i < 4; i++)
#pragma unroll
            for (int j = 0; j < 4; j++) acc[i][j] += dot4f(cv[i], bv[j]);
    }
    __syncthreads();
#pragma unroll
    for (int i = 0; i < 4; i++) {
        int t = ty*4 + i; float lt = sL[t];
#pragma unroll
        for (int j = 0; j < 4; j++) {
            int tau = tx*4 + j;
            sCG[t*68+tau] = (tau <= t) ? __expf(lt - sL[tau]) * sdt[tau] * acc[i][j] : 0.f;
        }
    }
    __syncthreads();

    float acc2[4][4];
#pragma unroll
    for (int i = 0; i < 4; i++)
#pragma unroll
        for (int j = 0; j < 4; j++) acc2[i][j] = 0.f;
    for (int tau = 0; tau < 64; tau += 4) {
        float xr[4][4];
#pragma unroll
        for (int s = 0; s < 4; s++) *(float4*)xr[s] = *(const float4*)&sX[(tau+s)*68 + tx*4];
#pragma unroll
        for (int i = 0; i < 4; i++) {
            float gr[4];
            *(float4*)gr = *(const float4*)&sCG[(ty*4+i)*68 + tau];
#pragma unroll
            for (int j = 0; j < 4; j++)
                acc2[i][j] += gr[0]*xr[0][j] + gr[1]*xr[1][j] + gr[2]*xr[2][j] + gr[3]*xr[3][j];
        }
    }
    const float Dh = Dv[h];
#pragma unroll
    for (int i = 0; i < 4; i++) {
        int t = ty*4 + i;
#pragma unroll
        for (int j = 0; j < 4; j++) {
            int p = tx*4 + j;
            g_y[(row0 + t) * DI + h*64 + p] = acc2[i][j] + Dh * sX[t*68+p];
        }
    }

    float acc3[4][4];
#pragma unroll
    for (int i = 0; i < 4; i++)
#pragma unroll
        for (int j = 0; j < 4; j++) acc3[i][j] = 0.f;
    for (int tau = 0; tau < 64; tau++) {
        float w = sW[tau];
        float xp[4], bn[4];
        *(float4*)xp = *(const float4*)&sX[tau*68 + ty*4];
        *(float4*)bn = *(const float4*)&sB[tau*68 + tx*4];
#pragma unroll
        for (int i = 0; i < 4; i++) {
            float xw = w * xp[i];
#pragma unroll
            for (int j = 0; j < 4; j++) acc3[i][j] += xw * bn[j];
        }
    }
#pragma unroll
    for (int i = 0; i < 4; i++)
#pragma unroll
        for (int j = 0; j < 4; j++)
            g_S[(size_t)bhc * 4096 + (ty*4+i) * 64 + (tx*4+j)] = acc3[i][j];
}

__global__ __launch_bounds__(256) void scan_seq()
{
    const int bh = blockIdx.x;
    const int tid = threadIdx.x;
    float s[16];
#pragma unroll
    for (int i = 0; i < 16; i++) s[i] = 0.f;
    const size_t base = (size_t)bh * NCHUNK * 4096;
    for (int c = 0; c < NCHUNK; c++) {
        float P = __expf(g_cl[((size_t)bh * NCHUNK + c) * 64 + 63]);
        size_t off = base + (size_t)c * 4096 + (size_t)tid * 16;
#pragma unroll
        for (int i = 0; i < 16; i += 4) {
            float4 Sv = *(const float4*)&g_S[off + i];
            *(float4*)&g_Sin[off + i] = make_float4(s[i], s[i+1], s[i+2], s[i+3]);
            s[i]   = s[i]  *P + Sv.x; s[i+1] = s[i+1]*P + Sv.y;
            s[i+2] = s[i+2]*P + Sv.z; s[i+3] = s[i+3]*P + Sv.w;
        }
    }
}

__global__ __launch_bounds__(256) void scan_inter()
{
    __shared__ float sC[64*68];
    __shared__ float sS[64*68];
    __shared__ float sE[64];
    const int bhc = blockIdx.x;
    const int bh = bhc >> 4, c = bhc & 15;
    const int b = bh >> 4, h = bh & 15;
    const int tid = threadIdx.x;
    const size_t row0 = (size_t)b * LL + c * 64;

    for (int i = tid; i < 64*64; i += 256) {
        int t = i >> 6, n = i & 63;
        sC[t*68+n] = g_xbc[(row0 + t) * CDIM + DI + DS + n];
        sS[t*68+n] = g_Sin[(size_t)bhc * 4096 + t * 64 + n];
    }
    if (tid < 64) sE[tid] = __expf(g_cl[(size_t)bhc * 64 + tid]);
    __syncthreads();

    const int ty = tid >> 4, tx = tid & 15;
    float acc[4][4];
#pragma unroll
    for (int i = 0; i < 4; i++)
#pragma unroll
        for (int j = 0; j < 4; j++) acc[i][j] = 0.f;
    for (int n = 0; n < 64; n += 4) {
        float4 cv[4], sv[4];
#pragma unroll
        for (int i = 0; i < 4; i++) cv[i] = *(const float4*)&sC[(ty*4+i)*68 + n];
#pragma unroll
        for (int j = 0; j < 4; j++) sv[j] = *(const float4*)&sS[(tx*4+j)*68 + n];
#pragma unroll
        for (int i = 0; i < 4; i++)
#pragma unroll
            for (int j = 0; j < 4; j++) acc[i][j] += dot4f(cv[i], sv[j]);
    }
#pragma unroll
    for (int i = 0; i < 4; i++) {
        int t = ty*4 + i; float e = sE[t];
#pragma unroll
        for (int j = 0; j < 4; j++) {
            size_t ix = (row0 + t) * DI + h*64 + tx*4 + j;
            g_y[ix] += e * acc[i][j];
        }
    }
}

// ======== norms / gating ========
__device__ __forceinline__ float block_reduce_sum(float v, float* red)
{
#pragma unroll
    for (int o = 16; o; o >>= 1) v += __shfl_xor_sync(0xffffffffu, v, o);
    if ((threadIdx.x & 31) == 0) red[threadIdx.x >> 5] = v;
    __syncthreads();
    float t = 0.f;
#pragma unroll
    for (int i = 0; i < 8; i++) t += red[i];
    return t;
}

__global__ __launch_bounds__(256) void gate_norm_kernel(const float* __restrict__ norm_w)
{
    __shared__ float red[8];
    int r = blockIdx.x;
    const float* zrow = g_zx + (size_t)r * DPROJ;
    const float* yrow = g_y + (size_t)r * DI;
    float vals[4]; float ss = 0.f;
#pragma unroll
    for (int i = 0; i < 4; i++) {
        int c = threadIdx.x + i*256;
        float z = zrow[c];
        float g = yrow[c] * (z / (1.f + expf(-z)));
        vals[i] = g; ss += g*g;
    }
    float sc = rsqrtf(block_reduce_sum(ss, red) * (1.f/1024.f) + EPSV);
    size_t rb = (size_t)r * 3 * DI;
#pragma unroll
    for (int i = 0; i < 4; i++) {
        int c = threadIdx.x + i*256;
        split3_act(g_gnb, rb, DI, c, vals[i] * sc * norm_w[c]);
    }
}

__global__ __launch_bounds__(256) void add_rms_hT_kernel(const float* __restrict__ u)
{
    __shared__ float red[8];
    int r = blockIdx.x;
    int b = r >> 10, l = r & (LL - 1);
    const float* ur = u + (size_t)r * DM;
    const float* mr = g_mo + (size_t)r * DM;
    float vals[2]; float ss = 0.f;
#pragma unroll
    for (int i = 0; i < 2; i++) {
        int d = threadIdx.x + i*256;
        float v = ur[d] + mr[d];
        vals[i] = v; ss += v*v;
    }
    float sc = rsqrtf(block_reduce_sum(ss, red) * (1.f/512.f) + EPSV);
#pragma unroll
    for (int i = 0; i < 2; i++) {
        int d = threadIdx.x + i*256;
        g_hT[(size_t)(b*DM + d) * LL + l] = vals[i] * sc;
    }
}

__global__ __launch_bounds__(256) void glu_kernel(const float* __restrict__ t,
    __nv_bfloat16* __restrict__ o, int half, int total)
{
    int idx = blockIdx.x * 256 + threadIdx.x;
    if (idx >= total) return;
    int r = idx / half, j = idx - r*half;
    const float* row = t + (size_t)r * 2 * half;
    float g = row[j], up = row[half + j];
    split3_act(o, (size_t)r * 3 * half, half, j, (g / (1.f + expf(-g))) * up);
}

__global__ __launch_bounds__(256) void add_rms_x2_kernel()
{
    __shared__ float red[8];
    int r = blockIdx.x;
    int b = r >> 9, d = r & (DM - 1);
    const float* hr = g_hT + (size_t)r * LL;
    const float* tr = g_t2 + (size_t)r * LL;
    float vals[4]; float ss = 0.f;
#pragma unroll
    for (int i = 0; i < 4; i++) {
        int l = threadIdx.x + i*256;
        float v = hr[l] + tr[l];
        vals[i] = v; ss += v*v;
    }
    float sc = rsqrtf(block_reduce_sum(ss, red) * (1.f/1024.f) + EPSV);
#pragma unroll
    for (int i = 0; i < 4; i++) {
        int l = threadIdx.x + i*256;
        g_h2[(size_t)(b*LL + l) * DM + d] = vals[i] * sc;
    }
}

__global__ __launch_bounds__(256) void final_rms_kernel(float* __restrict__ out)
{
    __shared__ float red[8];
    int r = blockIdx.x;
    const float* hr = g_h2 + (size_t)r * DM;
    const float* mr = g_m2 + (size_t)r * DM;
    float vals[2]; float ss = 0.f;
#pragma unroll
    for (int i = 0; i < 2; i++) {
        int d = threadIdx.x + i*256;
        float v = hr[d] + mr[d];
        vals[i] = v; ss += v*v;
    }
    float sc = rsqrtf(block_reduce_sum(ss, red) * (1.f/512.f) + EPSV);
#pragma unroll
    for (int i = 0; i < 2; i++) {
        int d = threadIdx.x + i*256;
        out[(size_t)r * DM + d] = vals[i] * sc;
    }
}

// ======== launch ========
#define GETSYM(p, s) cudaGetSymbolAddress((void**)&p, s)
extern "C" void kernel_launch(void* const* d_in, const int* in_sizes, int n_in,
                              void* d_out, int out_size)
{
    const float* u          = (const float*)d_in[0];
    const float* in_proj_w  = (const float*)d_in[1];
    const float* conv_w     = (const float*)d_in[2];
    const float* conv_b     = (const float*)d_in[3];
    const float* dt_bias    = (const float*)d_in[4];
    const float* A_log      = (const float*)d_in[5];
    const float* Dv         = (const float*)d_in[6];
    const float* norm_w     = (const float*)d_in[7];
    const float* out_proj_w = (const float*)d_in[8];
    const float* gu_t       = (const float*)d_in[9];
    const float* down_t     = (const float*)d_in[10];
    const float* gu_m       = (const float*)d_in[11];
    const float* down_m     = (const float*)d_in[12];
    float* out = (float*)d_out;

    float *zx, *mo, *hT, *t1, *t2, *h2, *m1, *m2;
    __nv_bfloat16 *ub, *gnb, *hTb, *tactb, *h2b, *mactb, *wip, *wop, *wgt, *wdt, *wgm, *wdm;
    GETSYM(zx, g_zx); GETSYM(mo, g_mo); GETSYM(hT, g_hT); GETSYM(t1, g_t1);
    GETSYM(t2, g_t2); GETSYM(h2, g_h2); GETSYM(m1, g_m1); GETSYM(m2, g_m2);
    GETSYM(ub, g_ub); GETSYM(gnb, g_gnb); GETSYM(hTb, g_hTb); GETSYM(tactb, g_tactb);
    GETSYM(h2b, g_h2b); GETSYM(mactb, g_mactb);
    GETSYM(wip, g_wip); GETSYM(wop, g_wop); GETSYM(wgt, g_wgt);
    GETSYM(wdt, g_wdt); GETSYM(wgm, g_wgm); GETSYM(wdm, g_wdm);

    cudaFuncSetAttribute(scan_chunk, cudaFuncAttributeMaxDynamicSharedMemorySize, 53248);
    cudaFuncSetAttribute(gemm_tc, cudaFuncAttributeMaxDynamicSharedMemorySize, G_SMEM);

    // weight + input splits (bf16 hi/lo, K'=3K)
    split_wt<<<(2304*512 + 255)/256, 256>>>(in_proj_w, wip, DPROJ, 2304, DM);
    split_wt<<<(512*1024 + 255)/256, 256>>>(out_proj_w, wop, DM, DM, DI);
    split_wt<<<(5632*1024 + 255)/256, 256>>>(gu_t, wgt, 2*IT, 2*IT, LL);
    split_wt<<<(1024*2816 + 255)/256, 256>>>(down_t, wdt, LL, LL, IT);
    split_wt<<<(3072*512 + 255)/256, 256>>>(gu_m, wgm, 2*IM, 2*IM, DM);
    split_wt<<<(512*1536 + 255)/256, 256>>>(down_m, wdm, DM, DM, IM);
    split_act<<<(NROWS*DM + 255)/256, 256>>>(u, ub, NROWS, DM);

    // ---- Mamba2 ----
    gemm_tc<<<dim3(18, 32), 256, G_SMEM>>>(ub, wip, zx, NROWS, DPROJ, 3*DM);
    dt_kernel<<<(NROWS*NH)/256, 256>>>(dt_bias, A_log);
    conv_kernel<<<(NROWS*CDIM + 255)/256, 256>>>(conv_w, conv_b);
    scan_chunk<<<BB*NH*NCHUNK, 256, 52992>>>(Dv);
    scan_seq<<<BB*NH, 256>>>();
    scan_inter<<<BB*NH*NCHUNK, 256>>>();
    gate_norm_kernel<<<NROWS, 256>>>(norm_w);
    gemm_tc<<<dim3(4, 32), 256, G_SMEM>>>(gnb, wop, mo, NROWS, DM, 3*DI);
    add_rms_hT_kernel<<<NROWS, 256>>>(u);
    split_act<<<(TROWS*LL + 255)/256, 256>>>(hT, hTb, TROWS, LL);

    // ---- token-mixing SwiGLU ----
    gemm_tc<<<dim3(44, 16), 256, G_SMEM>>>(hTb, wgt, t1, TROWS, 2*IT, 3*LL);
    glu_kernel<<<(TROWS*IT + 255)/256, 256>>>(t1, tactb, IT, TROWS*IT);
    gemm_tc<<<dim3(8, 16), 256, G_SMEM>>>(tactb, wdt, t2, TROWS, LL, 3*IT);
    add_rms_x2_kernel<<<TROWS, 256>>>();
    split_act<<<(NROWS*DM + 255)/256, 256>>>(h2, h2b, NROWS, DM);

    // ---- channel SwiGLU ----
    gemm_tc<<<dim3(24, 32), 256, G_SMEM>>>(h2b, wgm, m1, NROWS, 2*IM, 3*DM);
    glu_kernel<<<(NROWS*IM + 255)/256, 256>>>(m1, mactb, IM, NROWS*IM);
    gemm_tc<<<dim3(4, 32), 256, G_SMEM>>>(mactb, wdm, m2, NROWS, DM, 3*IM);
    final_rms_kernel<<<NROWS, 256>>>(out);
}

// round 15
// speedup vs baseline: 1.2189x; 1.0491x over previous
#include <cuda_runtime.h>
#include <cuda_bf16.h>
#include <math.h>
#include <stdint.h>

#define BB     4
#define LL     1024
#define DM     512
#define DI     1024
#define DS     64
#define NH     16
#define HD     64
#define CDIM   1152
#define DPROJ  2192
#define NROWS  (BB*LL)
#define TROWS  (BB*DM)
#define IT     2816
#define IM     1536
#define EPSV   1e-5f
#define NCHUNK 16

// ---- fp32 scratch ----
__device__ float g_zx  [(size_t)NROWS*DPROJ];
__device__ float g_dt  [(size_t)NROWS*NH];
__device__ float g_ldA [(size_t)NROWS*NH];
__device__ float g_xbc [(size_t)NROWS*CDIM];
__device__ float g_y   [(size_t)NROWS*DI];
__device__ float g_mo  [(size_t)NROWS*DM];
__device__ float g_hT  [(size_t)TROWS*LL];
__device__ float g_t1  [(size_t)TROWS*2*IT];
__device__ float g_t2  [(size_t)TROWS*LL];
__device__ float g_h2  [(size_t)NROWS*DM];
__device__ float g_m1  [(size_t)NROWS*2*IM];
__device__ float g_m2  [(size_t)NROWS*DM];
__device__ float g_S   [(size_t)BB*NH*NCHUNK*HD*DS];
__device__ float g_Sin [(size_t)BB*NH*NCHUNK*HD*DS];
__device__ float g_cl  [(size_t)BB*NH*NCHUNK*64];
// ---- bf16 split scratch (K'=3K) ----
__device__ __nv_bfloat16 g_ub   [(size_t)NROWS*3*DM];
__device__ __nv_bfloat16 g_gnb  [(size_t)NROWS*3*DI];
__device__ __nv_bfloat16 g_hTb  [(size_t)TROWS*3*LL];
__device__ __nv_bfloat16 g_tactb[(size_t)TROWS*3*IT];
__device__ __nv_bfloat16 g_h2b  [(size_t)NROWS*3*DM];
__device__ __nv_bfloat16 g_mactb[(size_t)NROWS*3*IM];
__device__ __nv_bfloat16 g_wip  [(size_t)2304*3*DM];
__device__ __nv_bfloat16 g_wop  [(size_t)DM*3*DI];
__device__ __nv_bfloat16 g_wgt  [(size_t)2*IT*3*LL];
__device__ __nv_bfloat16 g_wdt  [(size_t)LL*3*IT];
__device__ __nv_bfloat16 g_wgm  [(size_t)2*IM*3*DM];
__device__ __nv_bfloat16 g_wdm  [(size_t)DM*3*IM];

// ======== PTX helpers (baseline ISA, legal on compute_103) ========
__device__ __forceinline__ uint32_t smem_u32(const void* p) {
    uint32_t a;
    asm("{ .reg .u64 t; cvta.to.shared.u64 t, %1; cvt.u32.u64 %0, t; }" : "=r"(a) : "l"(p));
    return a;
}
__device__ __forceinline__ void cp16(uint32_t dst, const void* src) {
    asm volatile("cp.async.cg.shared.global [%0], [%1], 16;" :: "r"(dst), "l"(src));
}
__device__ __forceinline__ void ldsm4(uint32_t* r, uint32_t addr) {
    asm volatile("ldmatrix.sync.aligned.m8n8.x4.shared.b16 {%0,%1,%2,%3}, [%4];"
        : "=r"(r[0]), "=r"(r[1]), "=r"(r[2]), "=r"(r[3]) : "r"(addr));
}
__device__ __forceinline__ void mma16816(float* c, const uint32_t* a, const uint32_t* b) {
    asm volatile("mma.sync.aligned.m16n8k16.row.col.f32.bf16.bf16.f32 "
        "{%0,%1,%2,%3}, {%4,%5,%6,%7}, {%8,%9}, {%0,%1,%2,%3};"
        : "+f"(c[0]), "+f"(c[1]), "+f"(c[2]), "+f"(c[3])
        : "r"(a[0]), "r"(a[1]), "r"(a[2]), "r"(a[3]), "r"(b[0]), "r"(b[1]));
}

// ======== HMMA GEMM: 128x128x32 tile, 3-stage cp.async pipeline, occ 2 (R12, passing) ========
#define ASTRIDE 40
#define ATILE   (128*ASTRIDE*2)
#define STAGEB  (2*ATILE)
#define G_SMEM  (3*STAGEB)

__global__ __launch_bounds__(256, 2) void gemm_tc(
    const __nv_bfloat16* __restrict__ A, const __nv_bfloat16* __restrict__ W,
    float* __restrict__ C, int M, int N, int Kp)
{
    extern __shared__ __align__(16) char smem[];
    const int tid = threadIdx.x;
    const int m0 = blockIdx.y * 128, n0 = blockIdx.x * 128;
    const uint32_t sbase = smem_u32(smem);
    const int lane = tid & 31, warp = tid >> 5;
    const int wm = warp >> 2, wn = warp & 3;

    const int rA = tid >> 2;
    const int cByte = (tid & 3) * 16;
    const __nv_bfloat16* pA = A + (size_t)(m0 + rA) * Kp + (tid & 3) * 8;
    const __nv_bfloat16* pB = W + (size_t)(n0 + rA) * Kp + (tid & 3) * 8;
    const uint32_t dA0 = sbase + rA * 80 + cByte;
    const uint32_t dB0 = dA0 + ATILE;

    const int g = lane >> 3, r = lane & 7;
    const uint32_t aAddr = sbase + (uint32_t)(((wm*64 + (g&1)*8 + r) * ASTRIDE + (g>>1)*8) * 2);
    const uint32_t bAddr = sbase + ATILE + (uint32_t)(((wn*32 + (g>>1)*8 + r) * ASTRIDE + (g&1)*8) * 2);

    float acc[4][4][4];
#pragma unroll
    for (int i = 0; i < 4; i++)
#pragma unroll
        for (int j = 0; j < 4; j++)
#pragma unroll
            for (int k = 0; k < 4; k++) acc[i][j][k] = 0.f;

    const int KT = Kp >> 5;

#define G_LOAD(kt) do { \
    const uint32_t _so = ((kt) % 3) * STAGEB; \
    const size_t _ko = (size_t)(kt) * 32; \
    cp16(dA0 + _so, pA + _ko);          cp16(dA0 + _so + 64*80, pA + _ko + (size_t)64 * Kp); \
    cp16(dB0 + _so, pB + _ko);          cp16(dB0 + _so + 64*80, pB + _ko + (size_t)64 * Kp); \
    asm volatile("cp.async.commit_group;"); \
} while (0)

    G_LOAD(0);
    G_LOAD(1);

    for (int kt = 0; kt < KT; kt++) {
        asm volatile("cp.async.wait_group 1;");
        __syncthreads();
        if (kt + 2 < KT) { G_LOAD(kt + 2); }
        else { asm volatile("cp.async.commit_group;"); }
        const uint32_t so = (kt % 3) * STAGEB;
#pragma unroll
        for (int ks = 0; ks < 2; ks++) {
            uint32_t a[4][4], b[2][4];
#pragma unroll
            for (int mf = 0; mf < 4; mf++) ldsm4(a[mf], aAddr + so + mf*1280 + ks*32);
#pragma unroll
            for (int jp = 0; jp < 2; jp++) ldsm4(b[jp], bAddr + so + jp*1280 + ks*32);
#pragma unroll
            for (int mf = 0; mf < 4; mf++)
#pragma unroll
                for (int nf = 0; nf < 4; nf++)
                    mma16816(acc[mf][nf], a[mf], &b[nf >> 1][(nf & 1) * 2]);
        }
    }
#undef G_LOAD

    const int crow = lane >> 2, ccol = (lane & 3) * 2;
#pragma unroll
    for (int mf = 0; mf < 4; mf++) {
        const int row = m0 + wm*64 + mf*16 + crow;
#pragma unroll
        for (int nf = 0; nf < 4; nf++) {
            const int col = n0 + wn*32 + nf*8 + ccol;
            if (col < N) {
                float2 v0 = make_float2(acc[mf][nf][0], acc[mf][nf][1]);
                float2 v1 = make_float2(acc[mf][nf][2], acc[mf][nf][3]);
                *(float2*)&C[(size_t)row * N + col]       = v0;
                *(float2*)&C[(size_t)(row + 8) * N + col] = v1;
            }
        }
    }
}

// ======== bf16 splits (vectorized x4; per-element math identical to scalar) ========
__device__ __forceinline__ void split3_act(__nv_bfloat16* dst, size_t rb, int K, int k, float v) {
    __nv_bfloat16 hi = __float2bfloat16(v);
    __nv_bfloat16 lo = __float2bfloat16(v - __bfloat162float(hi));
    dst[rb + k] = hi; dst[rb + K + k] = lo; dst[rb + 2*K + k] = hi;
}

// vector helper: given 4 fp32, write hi x4 / lo x4 at dst+off (as 2x bf162 each)
__device__ __forceinline__ void store_hilo4(__nv_bfloat16* dst, size_t off_hi, size_t off_lo,
                                            float v0, float v1, float v2, float v3)
{
    __nv_bfloat16 h0 = __float2bfloat16(v0), h1 = __float2bfloat16(v1);
    __nv_bfloat16 h2 = __float2bfloat16(v2), h3 = __float2bfloat16(v3);
    __nv_bfloat16 l0 = __float2bfloat16(v0 - __bfloat162float(h0));
    __nv_bfloat16 l1 = __float2bfloat16(v1 - __bfloat162float(h1));
    __nv_bfloat16 l2 = __float2bfloat16(v2 - __bfloat162float(h2));
    __nv_bfloat16 l3 = __float2bfloat16(v3 - __bfloat162float(h3));
    *(__nv_bfloat162*)(dst + off_hi)     = __nv_bfloat162(h0, h1);
    *(__nv_bfloat162*)(dst + off_hi + 2) = __nv_bfloat162(h2, h3);
    *(__nv_bfloat162*)(dst + off_lo)     = __nv_bfloat162(l0, l1);
    *(__nv_bfloat162*)(dst + off_lo + 2) = __nv_bfloat162(l2, l3);
}

// activation split: [hi, lo, hi]
__global__ __launch_bounds__(256) void split_act(const float* __restrict__ src,
    __nv_bfloat16* __restrict__ dst, int rows, int K)
{
    int i = blockIdx.x * 256 + threadIdx.x;           // groups of 4
    int kq = K >> 2;
    if (i >= rows * kq) return;
    int r = i / kq, k = (i - r * kq) * 4;
    float4 v = *(const float4*)(src + (size_t)r * K + k);
    size_t b = (size_t)r * 3 * K + k;
    store_hilo4(dst, b, b + K, v.x, v.y, v.z, v.w);
    // third segment = hi again
    __nv_bfloat162 h01 = __nv_bfloat162(__float2bfloat16(v.x), __float2bfloat16(v.y));
    __nv_bfloat162 h23 = __nv_bfloat162(__float2bfloat16(v.z), __float2bfloat16(v.w));
    *(__nv_bfloat162*)(dst + b + 2*K)     = h01;
    *(__nv_bfloat162*)(dst + b + 2*K + 2) = h23;
}

// weight split: [hi, hi, lo], rows padded with zeros to Npad
__global__ __launch_bounds__(256) void split_wt(const float* __restrict__ src,
    __nv_bfloat16* __restrict__ dst, int N, int Npad, int K)
{
    int i = blockIdx.x * 256 + threadIdx.x;
    int kq = K >> 2;
    if (i >= Npad * kq) return;
    int r = i / kq, k = (i - r * kq) * 4;
    float4 v;
    if (r < N) v = *(const float4*)(src + (size_t)r * K + k);
    else       v = make_float4(0.f, 0.f, 0.f, 0.f);
    size_t b = (size_t)r * 3 * K + k;
    store_hilo4(dst, b, b + 2*K, v.x, v.y, v.z, v.w);   // hi at 0, lo at 2K
    __nv_bfloat162 h01 = __nv_bfloat162(__float2bfloat16(v.x), __float2bfloat16(v.y));
    __nv_bfloat162 h23 = __nv_bfloat162(__float2bfloat16(v.z), __float2bfloat16(v.w));
    *(__nv_bfloat162*)(dst + b + K)     = h01;          // hi at K
    *(__nv_bfloat162*)(dst + b + K + 2) = h23;
}

// ======== Mamba pointwise ========
__global__ __launch_bounds__(256) void dt_kernel(const float* __restrict__ dt_bias, const float* __restrict__ A_log)
{
    int idx = blockIdx.x * 256 + threadIdx.x;
    int h = idx & 15, r = idx >> 4;
    float v = g_zx[(size_t)r * DPROJ + (DPROJ - NH) + h] + dt_bias[h];
    float dt = (v > 20.f) ? v : log1pf(expf(v));
    g_dt[idx] = dt;
    g_ldA[idx] = -dt * expf(A_log[h]);
}
__global__ __launch_bounds__(256) void conv_kernel(const float* __restrict__ cw, const float* __restrict__ cb)
{
    int idx = blockIdx.x * 256 + threadIdx.x;
    if (idx >= NROWS * CDIM) return;
    int c = idx % CDIM, r = idx / CDIM, l = r & (LL - 1);
    float acc = cb[c];
#pragma unroll
    for (int i = 0; i < 4; i++) {
        int li = l - 3 + i;
        if (li >= 0) acc += g_zx[(size_t)(r - 3 + i) * DPROJ + DI + c] * cw[c * 4 + i];
    }
    g_xbc[idx] = acc / (1.f + expf(-acc));
}

// ======== chunked scan ========
__device__ __forceinline__ float dot4f(float4 a, float4 b) { return a.x*b.x + a.y*b.y + a.z*b.z + a.w*b.w; }

__global__ __launch_bounds__(256) void scan_chunk(const float* __restrict__ Dv)
{
    extern __shared__ float sm[];
    float* sX  = sm;
    float* sB  = sm + 64*68;
    float* sCG = sm + 2*64*68;
    float* sdt = sm + 3*64*68;
    float* sL  = sdt + 64;
    float* sW  = sL + 64;
    const int bhc = blockIdx.x;
    const int bh = bhc >> 4, c = bhc & 15;
    const int b = bh >> 4, h = bh & 15;
    const int tid = threadIdx.x;
    const size_t row0 = (size_t)b * LL + c * 64;

    for (int i = tid; i < 64*64; i += 256) {
        int t = i >> 6, n = i & 63;
        size_t rb = (row0 + t) * CDIM;
        sX[t*68+n]  = g_xbc[rb + h*64 + n];
        sB[t*68+n]  = g_xbc[rb + DI + n];
        sCG[t*68+n] = g_xbc[rb + DI + DS + n];
    }
    if (tid < 64) {
        size_t rr = (row0 + tid) * NH + h;
        sdt[tid] = g_dt[rr]; sL[tid] = g_ldA[rr];
    }
    __syncthreads();
    if (tid == 0) { float a = 0.f; for (int t = 0; t < 64; t++) { a += sL[t]; sL[t] = a; } }
    __syncthreads();
    if (tid < 64) {
        sW[tid] = __expf(sL[63] - sL[tid]) * sdt[tid];
        g_cl[(size_t)bhc * 64 + tid] = sL[tid];
    }
    __syncthreads();

    const int ty = tid >> 4, tx = tid & 15;
    float acc[4][4];
#pragma unroll
    for (int i = 0; i < 4; i++)
#pragma unroll
        for (int j = 0; j < 4; j++) acc[i][j] = 0.f;
    for (int n = 0; n < 64; n += 4) {
        float4 cv[4], bv[4];
#pragma unroll
        for (int i = 0; i < 4; i++) cv[i] = *(const float4*)&sCG[(ty*4+i)*68 + n];
#pragma unroll
        for (int j = 0; j < 4; j++) bv[j] = *(const float4*)&sB[(tx*4+j)*68 + n];
#pragma unroll
        for (int i = 0; i < 4; i++)
#pragma unroll
            for (int j = 0; j < 4; j++) acc[i][j] += dot4f(cv[i], bv[j]);
    }
    __syncthreads();
#pragma unroll
    for (int i = 0; i < 4; i++) {
        int t = ty*4 + i; float lt = sL[t];
#pragma unroll
        for (int j = 0; j < 4; j++) {
            int tau = tx*4 + j;
            sCG[t*68+tau] = (tau <= t) ? __expf(lt - sL[tau]) * sdt[tau] * acc[i][j] : 0.f;
        }
    }
    __syncthreads();

    float acc2[4][4];
#pragma unroll
    for (int i = 0; i < 4; i++)
#pragma unroll
        for (int j = 0; j < 4; j++) acc2[i][j] = 0.f;
    for (int tau = 0; tau < 64; tau += 4) {
        float xr[4][4];
#pragma unroll
        for (int s = 0; s < 4; s++) *(float4*)xr[s] = *(const float4*)&sX[(tau+s)*68 + tx*4];
#pragma unroll
        for (int i = 0; i < 4; i++) {
            float gr[4];
            *(float4*)gr = *(const float4*)&sCG[(ty*4+i)*68 + tau];
#pragma unroll
            for (int j = 0; j < 4; j++)
                acc2[i][j] += gr[0]*xr[0][j] + gr[1]*xr[1][j] + gr[2]*xr[2][j] + gr[3]*xr[3][j];
        }
    }
    const float Dh = Dv[h];
#pragma unroll
    for (int i = 0; i < 4; i++) {
        int t = ty*4 + i;
#pragma unroll
        for (int j = 0; j < 4; j++) {
            int p = tx*4 + j;
            g_y[(row0 + t) * DI + h*64 + p] = acc2[i][j] + Dh * sX[t*68+p];
        }
    }

    float acc3[4][4];
#pragma unroll
    for (int i = 0; i < 4; i++)
#pragma unroll
        for (int j = 0; j < 4; j++) acc3[i][j] = 0.f;
    for (int tau = 0; tau < 64; tau++) {
        float w = sW[tau];
        float xp[4], bn[4];
        *(float4*)xp = *(const float4*)&sX[tau*68 + ty*4];
        *(float4*)bn = *(const float4*)&sB[tau*68 + tx*4];
#pragma unroll
        for (int i = 0; i < 4; i++) {
            float xw = w * xp[i];
#pragma unroll
            for (int j = 0; j < 4; j++) acc3[i][j] += xw * bn[j];
        }
    }
#pragma unroll
    for (int i = 0; i < 4; i++)
#pragma unroll
        for (int j = 0; j < 4; j++)
            g_S[(size_t)bhc * 4096 + (ty*4+i) * 64 + (tx*4+j)] = acc3[i][j];
}

__global__ __launch_bounds__(256) void scan_seq()
{
    const int bh = blockIdx.x;
    const int tid = threadIdx.x;
    float s[16];
#pragma unroll
    for (int i = 0; i < 16; i++) s[i] = 0.f;
    const size_t base = (size_t)bh * NCHUNK * 4096;
    for (int c = 0; c < NCHUNK; c++) {
        float P = __expf(g_cl[((size_t)bh * NCHUNK + c) * 64 + 63]);
        size_t off = base + (size_t)c * 4096 + (size_t)tid * 16;
#pragma unroll
        for (int i = 0; i < 16; i += 4) {
            float4 Sv = *(const float4*)&g_S[off + i];
            *(float4*)&g_Sin[off + i] = make_float4(s[i], s[i+1], s[i+2], s[i+3]);
            s[i]   = s[i]  *P + Sv.x; s[i+1] = s[i+1]*P + Sv.y;
            s[i+2] = s[i+2]*P + Sv.z; s[i+3] = s[i+3]*P + Sv.w;
        }
    }
}

__global__ __launch_bounds__(256) void scan_inter()
{
    __shared__ float sC[64*68];
    __shared__ float sS[64*68];
    __shared__ float sE[64];
    const int bhc = blockIdx.x;
    const int bh = bhc >> 4, c = bhc & 15;
    const int b = bh >> 4, h = bh & 15;
    const int tid = threadIdx.x;
    const size_t row0 = (size_t)b * LL + c * 64;

    for (int i = tid; i < 64*64; i += 256) {
        int t = i >> 6, n = i & 63;
        sC[t*68+n] = g_xbc[(row0 + t) * CDIM + DI + DS + n];
        sS[t*68+n] = g_Sin[(size_t)bhc * 4096 + t * 64 + n];
    }
    if (tid < 64) sE[tid] = __expf(g_cl[(size_t)bhc * 64 + tid]);
    __syncthreads();

    const int ty = tid >> 4, tx = tid & 15;
    float acc[4][4];
#pragma unroll
    for (int i = 0; i < 4; i++)
#pragma unroll
        for (int j = 0; j < 4; j++) acc[i][j] = 0.f;
    for (int n = 0; n < 64; n += 4) {
        float4 cv[4], sv[4];
#pragma unroll
        for (int i = 0; i < 4; i++) cv[i] = *(const float4*)&sC[(ty*4+i)*68 + n];
#pragma unroll
        for (int j = 0; j < 4; j++) sv[j] = *(const float4*)&sS[(tx*4+j)*68 + n];
#pragma unroll
        for (int i = 0; i < 4; i++)
#pragma unroll
            for (int j = 0; j < 4; j++) acc[i][j] += dot4f(cv[i], sv[j]);
    }
#pragma unroll
    for (int i = 0; i < 4; i++) {
        int t = ty*4 + i; float e = sE[t];
#pragma unroll
        for (int j = 0; j < 4; j++) {
            size_t ix = (row0 + t) * DI + h*64 + tx*4 + j;
            g_y[ix] += e * acc[i][j];
        }
    }
}

// ======== norms / gating / GLU ========
__device__ __forceinline__ float block_reduce_sum(float v, float* red)
{
#pragma unroll
    for (int o = 16; o; o >>= 1) v += __shfl_xor_sync(0xffffffffu, v, o);
    if ((threadIdx.x & 31) == 0) red[threadIdx.x >> 5] = v;
    __syncthreads();
    float t = 0.f;
#pragma unroll
    for (int i = 0; i < 8; i++) t += red[i];
    return t;
}

__global__ __launch_bounds__(256) void gate_norm_kernel(const float* __restrict__ norm_w)
{
    __shared__ float red[8];
    int r = blockIdx.x;
    const float* zrow = g_zx + (size_t)r * DPROJ;
    const float* yrow = g_y + (size_t)r * DI;
    float vals[4]; float ss = 0.f;
#pragma unroll
    for (int i = 0; i < 4; i++) {
        int c = threadIdx.x + i*256;
        float z = zrow[c];
        float g = yrow[c] * (z / (1.f + expf(-z)));
        vals[i] = g; ss += g*g;
    }
    float sc = rsqrtf(block_reduce_sum(ss, red) * (1.f/1024.f) + EPSV);
    size_t rb = (size_t)r * 3 * DI;
#pragma unroll
    for (int i = 0; i < 4; i++) {
        int c = threadIdx.x + i*256;
        split3_act(g_gnb, rb, DI, c, vals[i] * sc * norm_w[c]);
    }
}

__global__ __launch_bounds__(256) void add_rms_hT_kernel(const float* __restrict__ u)
{
    __shared__ float red[8];
    int r = blockIdx.x;
    int b = r >> 10, l = r & (LL - 1);
    const float* ur = u + (size_t)r * DM;
    const float* mr = g_mo + (size_t)r * DM;
    float vals[2]; float ss = 0.f;
#pragma unroll
    for (int i = 0; i < 2; i++) {
        int d = threadIdx.x + i*256;
        float v = ur[d] + mr[d];
        vals[i] = v; ss += v*v;
    }
    float sc = rsqrtf(block_reduce_sum(ss, red) * (1.f/512.f) + EPSV);
#pragma unroll
    for (int i = 0; i < 2; i++) {
        int d = threadIdx.x + i*256;
        g_hT[(size_t)(b*DM + d) * LL + l] = vals[i] * sc;
    }
}

// GLU vectorized x4: reads gate/up float4, writes bf16 3-split
__global__ __launch_bounds__(256) void glu_kernel(const float* __restrict__ t,
    __nv_bfloat16* __restrict__ o, int half, int total4)
{
    int i = blockIdx.x * 256 + threadIdx.x;
    if (i >= total4) return;
    int hq = half >> 2;
    int r = i / hq, j = (i - r * hq) * 4;
    const float* row = t + (size_t)r * 2 * half;
    float4 gv = *(const float4*)(row + j);
    float4 uv = *(const float4*)(row + half + j);
    float v0 = (gv.x / (1.f + expf(-gv.x))) * uv.x;
    float v1 = (gv.y / (1.f + expf(-gv.y))) * uv.y;
    float v2 = (gv.z / (1.f + expf(-gv.z))) * uv.z;
    float v3 = (gv.w / (1.f + expf(-gv.w))) * uv.w;
    size_t b = (size_t)r * 3 * half + j;
    store_hilo4(o, b, b + half, v0, v1, v2, v3);            // hi at 0, lo at half
    __nv_bfloat162 h01 = __nv_bfloat162(__float2bfloat16(v0), __float2bfloat16(v1));
    __nv_bfloat162 h23 = __nv_bfloat162(__float2bfloat16(v2), __float2bfloat16(v3));
    *(__nv_bfloat162*)(o + b + 2*half)     = h01;           // hi at 2*half
    *(__nv_bfloat162*)(o + b + 2*half + 2) = h23;
}

__global__ __launch_bounds__(256) void add_rms_x2_kernel()
{
    __shared__ float red[8];
    int r = blockIdx.x;
    int b = r >> 9, d = r & (DM - 1);
    const float* hr = g_hT + (size_t)r * LL;
    const float* tr = g_t2 + (size_t)r * LL;
    float vals[4]; float ss = 0.f;
#pragma unroll
    for (int i = 0; i < 4; i++) {
        int l = threadIdx.x + i*256;
        float v = hr[l] + tr[l];
        vals[i] = v; ss += v*v;
    }
    float sc = rsqrtf(block_reduce_sum(ss, red) * (1.f/1024.f) + EPSV);
#pragma unroll
    for (int i = 0; i < 4; i++) {
        int l = threadIdx.x + i*256;
        g_h2[(size_t)(b*LL + l) * DM + d] = vals[i] * sc;
    }
}

__global__ __launch_bounds__(256) void final_rms_kernel(float* __restrict__ out)
{
    __shared__ float red[8];
    int r = blockIdx.x;
    const float* hr = g_h2 + (size_t)r * DM;
    const float* mr = g_m2 + (size_t)r * DM;
    float vals[2]; float ss = 0.f;
#pragma unroll
    for (int i = 0; i < 2; i++) {
        int d = threadIdx.x + i*256;
        float v = hr[d] + mr[d];
        vals[i] = v; ss += v*v;
    }
    float sc = rsqrtf(block_reduce_sum(ss, red) * (1.f/512.f) + EPSV);
#pragma unroll
    for (int i = 0; i < 2; i++) {
        int d = threadIdx.x + i*256;
        out[(size_t)r * DM + d] = vals[i] * sc;
    }
}

// ======== launch ========
#define GETSYM(p, s) cudaGetSymbolAddress((void**)&p, s)
extern "C" void kernel_launch(void* const* d_in, const int* in_sizes, int n_in,
                              void* d_out, int out_size)
{
    const float* u          = (const float*)d_in[0];
    const float* in_proj_w  = (const float*)d_in[1];
    const float* conv_w     = (const float*)d_in[2];
    const float* conv_b     = (const float*)d_in[3];
    const float* dt_bias    = (const float*)d_in[4];
    const float* A_log      = (const float*)d_in[5];
    const float* Dv         = (const float*)d_in[6];
    const float* norm_w     = (const float*)d_in[7];
    const float* out_proj_w = (const float*)d_in[8];
    const float* gu_t       = (const float*)d_in[9];
    const float* down_t     = (const float*)d_in[10];
    const float* gu_m       = (const float*)d_in[11];
    const float* down_m     = (const float*)d_in[12];
    float* out = (float*)d_out;

    float *zx, *mo, *hT, *t1, *t2, *h2, *m1, *m2;
    __nv_bfloat16 *ub, *gnb, *hTb, *tactb, *h2b, *mactb, *wip, *wop, *wgt, *wdt, *wgm, *wdm;
    GETSYM(zx, g_zx); GETSYM(mo, g_mo); GETSYM(hT, g_hT); GETSYM(t1, g_t1);
    GETSYM(t2, g_t2); GETSYM(h2, g_h2); GETSYM(m1, g_m1); GETSYM(m2, g_m2);
    GETSYM(ub, g_ub); GETSYM(gnb, g_gnb); GETSYM(hTb, g_hTb); GETSYM(tactb, g_tactb);
    GETSYM(h2b, g_h2b); GETSYM(mactb, g_mactb);
    GETSYM(wip, g_wip); GETSYM(wop, g_wop); GETSYM(wgt, g_wgt);
    GETSYM(wdt, g_wdt); GETSYM(wgm, g_wgm); GETSYM(wdm, g_wdm);

    cudaFuncSetAttribute(scan_chunk, cudaFuncAttributeMaxDynamicSharedMemorySize, 53248);
    cudaFuncSetAttribute(gemm_tc, cudaFuncAttributeMaxDynamicSharedMemorySize, G_SMEM);

    // weight + input splits (bf16 hi/lo, K'=3K), vectorized x4
    split_wt<<<(2304*(512/4) + 255)/256, 256>>>(in_proj_w, wip, DPROJ, 2304, DM);
    split_wt<<<(512*(1024/4) + 255)/256, 256>>>(out_proj_w, wop, DM, DM, DI);
    split_wt<<<(5632*(1024/4) + 255)/256, 256>>>(gu_t, wgt, 2*IT, 2*IT, LL);
    split_wt<<<(1024*(2816/4) + 255)/256, 256>>>(down_t, wdt, LL, LL, IT);
    split_wt<<<(3072*(512/4) + 255)/256, 256>>>(gu_m, wgm, 2*IM, 2*IM, DM);
    split_wt<<<(512*(1536/4) + 255)/256, 256>>>(down_m, wdm, DM, DM, IM);
    split_act<<<(NROWS*(DM/4) + 255)/256, 256>>>(u, ub, NROWS, DM);

    // ---- Mamba2 ----
    gemm_tc<<<dim3(18, 32), 256, G_SMEM>>>(ub, wip, zx, NROWS, DPROJ, 3*DM);
    dt_kernel<<<(NROWS*NH)/256, 256>>>(dt_bias, A_log);
    conv_kernel<<<(NROWS*CDIM + 255)/256, 256>>>(conv_w, conv_b);
    scan_chunk<<<BB*NH*NCHUNK, 256, 52992>>>(Dv);
    scan_seq<<<BB*NH, 256>>>();
    scan_inter<<<BB*NH*NCHUNK, 256>>>();
    gate_norm_kernel<<<NROWS, 256>>>(norm_w);
    gemm_tc<<<dim3(4, 32), 256, G_SMEM>>>(gnb, wop, mo, NROWS, DM, 3*DI);
    add_rms_hT_kernel<<<NROWS, 256>>>(u);
    split_act<<<(TROWS*(LL/4) + 255)/256, 256>>>(hT, hTb, TROWS, LL);

    // ---- token-mixing SwiGLU ----
    gemm_tc<<<dim3(44, 16), 256, G_SMEM>>>(hTb, wgt, t1, TROWS, 2*IT, 3*LL);
    glu_kernel<<<(TROWS*(IT/4) + 255)/256, 256>>>(t1, tactb, IT, TROWS*(IT/4));
    gemm_tc<<<dim3(8, 16), 256, G_SMEM>>>(tactb, wdt, t2, TROWS, LL, 3*IT);
    add_rms_x2_kernel<<<TROWS, 256>>>();
    split_act<<<(NROWS*(DM/4) + 255)/256, 256>>>(h2, h2b, NROWS, DM);

    // ---- channel SwiGLU ----
    gemm_tc<<<dim3(24, 32), 256, G_SMEM>>>(h2b, wgm, m1, NROWS, 2*IM, 3*DM);
    glu_kernel<<<(NROWS*(IM/4) + 255)/256, 256>>>(m1, mactb, IM, NROWS*(IM/4));
    gemm_tc<<<dim3(4, 32), 256, G_SMEM>>>(mactb, wdm, m2, NROWS, DM, 3*IM);
    final_rms_kernel<<<NROWS, 256>>>(out);
}

// round 17
// speedup vs baseline: 1.3031x; 1.0691x over previous
#include <cuda_runtime.h>
#include <cuda_bf16.h>
#include <math.h>
#include <stdint.h>

#define BB     4
#define LL     1024
#define DM     512
#define DI     1024
#define DS     64
#define NH     16
#define HD     64
#define CDIM   1152
#define DPROJ  2192
#define NROWS  (BB*LL)
#define TROWS  (BB*DM)
#define IT     2816
#define IM     1536
#define EPSV   1e-5f
#define NCHUNK 16

// ---- fp32 scratch ----
__device__ float g_zx  [(size_t)NROWS*DPROJ];
__device__ float g_dt  [(size_t)NROWS*NH];
__device__ float g_ldA [(size_t)NROWS*NH];
__device__ float g_xbc [(size_t)NROWS*CDIM];
__device__ float g_y   [(size_t)NROWS*DI];
__device__ float g_mo  [(size_t)NROWS*DM];
__device__ float g_mo2 [(size_t)NROWS*DM];
__device__ float g_hT  [(size_t)TROWS*LL];
__device__ float g_t1  [(size_t)TROWS*2*IT];
__device__ float g_t2  [(size_t)TROWS*LL];
__device__ float g_t22 [(size_t)TROWS*LL];
__device__ float g_h2  [(size_t)NROWS*DM];
__device__ float g_m1  [(size_t)NROWS*2*IM];
__device__ float g_m2  [(size_t)NROWS*DM];
__device__ float g_m22 [(size_t)NROWS*DM];
__device__ float g_S   [(size_t)BB*NH*NCHUNK*HD*DS];
__device__ float g_Sin [(size_t)BB*NH*NCHUNK*HD*DS];
__device__ float g_cl  [(size_t)BB*NH*NCHUNK*64];
// ---- bf16 split scratch (K'=3K) ----
__device__ __nv_bfloat16 g_ub   [(size_t)NROWS*3*DM];
__device__ __nv_bfloat16 g_gnb  [(size_t)NROWS*3*DI];
__device__ __nv_bfloat16 g_hTb  [(size_t)TROWS*3*LL];
__device__ __nv_bfloat16 g_tactb[(size_t)TROWS*3*IT];
__device__ __nv_bfloat16 g_h2b  [(size_t)NROWS*3*DM];
__device__ __nv_bfloat16 g_mactb[(size_t)NROWS*3*IM];
__device__ __nv_bfloat16 g_wip  [(size_t)2304*3*DM];
__device__ __nv_bfloat16 g_wop  [(size_t)DM*3*DI];
__device__ __nv_bfloat16 g_wgt  [(size_t)2*IT*3*LL];
__device__ __nv_bfloat16 g_wdt  [(size_t)LL*3*IT];
__device__ __nv_bfloat16 g_wgm  [(size_t)2*IM*3*DM];
__device__ __nv_bfloat16 g_wdm  [(size_t)DM*3*IM];

// ======== PTX helpers (baseline ISA, legal on compute_103) ========
__device__ __forceinline__ uint32_t smem_u32(const void* p) {
    uint32_t a;
    asm("{ .reg .u64 t; cvta.to.shared.u64 t, %1; cvt.u32.u64 %0, t; }" : "=r"(a) : "l"(p));
    return a;
}
__device__ __forceinline__ void cp16(uint32_t dst, const void* src) {
    asm volatile("cp.async.cg.shared.global [%0], [%1], 16;" :: "r"(dst), "l"(src));
}
__device__ __forceinline__ void ldsm4(uint32_t* r, uint32_t addr) {
    asm volatile("ldmatrix.sync.aligned.m8n8.x4.shared.b16 {%0,%1,%2,%3}, [%4];"
        : "=r"(r[0]), "=r"(r[1]), "=r"(r[2]), "=r"(r[3]) : "r"(addr));
}
__device__ __forceinline__ void mma16816(float* c, const uint32_t* a, const uint32_t* b) {
    asm volatile("mma.sync.aligned.m16n8k16.row.col.f32.bf16.bf16.f32 "
        "{%0,%1,%2,%3}, {%4,%5,%6,%7}, {%8,%9}, {%0,%1,%2,%3};"
        : "+f"(c[0]), "+f"(c[1]), "+f"(c[2]), "+f"(c[3])
        : "r"(a[0]), "r"(a[1]), "r"(a[2]), "r"(a[3]), "r"(b[0]), "r"(b[1]));
}

// ======== HMMA GEMM: 128x128x32 tile, 3-stage cp.async, optional split-K=2 via blockIdx.z ========
#define ASTRIDE 40
#define ATILE   (128*ASTRIDE*2)
#define STAGEB  (2*ATILE)
#define G_SMEM  (3*STAGEB)

__global__ __launch_bounds__(256, 2) void gemm_tc(
    const __nv_bfloat16* __restrict__ A, const __nv_bfloat16* __restrict__ W,
    float* __restrict__ C, float* __restrict__ C2, int M, int N, int Kp)
{
    extern __shared__ __align__(16) char smem[];
    const int tid = threadIdx.x;
    const int m0 = blockIdx.y * 128, n0 = blockIdx.x * 128;
    const uint32_t sbase = smem_u32(smem);
    const int lane = tid & 31, warp = tid >> 5;
    const int wm = warp >> 2, wn = warp & 3;

    // split-K: z=0 -> first half K into C; z=1 -> second half into C2
    const int halfK = (gridDim.z == 2) ? (Kp >> 1) : Kp;
    const size_t koff = (size_t)blockIdx.z * halfK;
    float* Cout = (blockIdx.z == 1) ? C2 : C;

    const int rA = tid >> 2;
    const int cByte = (tid & 3) * 16;
    const __nv_bfloat16* pA = A + (size_t)(m0 + rA) * Kp + (tid & 3) * 8 + koff;
    const __nv_bfloat16* pB = W + (size_t)(n0 + rA) * Kp + (tid & 3) * 8 + koff;
    const uint32_t dA0 = sbase + rA * 80 + cByte;
    const uint32_t dB0 = dA0 + ATILE;

    const int g = lane >> 3, r = lane & 7;
    const uint32_t aAddr = sbase + (uint32_t)(((wm*64 + (g&1)*8 + r) * ASTRIDE + (g>>1)*8) * 2);
    const uint32_t bAddr = sbase + ATILE + (uint32_t)(((wn*32 + (g>>1)*8 + r) * ASTRIDE + (g&1)*8) * 2);

    float acc[4][4][4];
#pragma unroll
    for (int i = 0; i < 4; i++)
#pragma unroll
        for (int j = 0; j < 4; j++)
#pragma unroll
            for (int k = 0; k < 4; k++) acc[i][j][k] = 0.f;

    const int KT = halfK >> 5;

#define G_LOAD(kt) do { \
    const uint32_t _so = ((kt) % 3) * STAGEB; \
    const size_t _ko = (size_t)(kt) * 32; \
    cp16(dA0 + _so, pA + _ko);          cp16(dA0 + _so + 64*80, pA + _ko + (size_t)64 * Kp); \
    cp16(dB0 + _so, pB + _ko);          cp16(dB0 + _so + 64*80, pB + _ko + (size_t)64 * Kp); \
    asm volatile("cp.async.commit_group;"); \
} while (0)

    G_LOAD(0);
    G_LOAD(1);

    for (int kt = 0; kt < KT; kt++) {
        asm volatile("cp.async.wait_group 1;");
        __syncthreads();
        if (kt + 2 < KT) { G_LOAD(kt + 2); }
        else { asm volatile("cp.async.commit_group;"); }
        const uint32_t so = (kt % 3) * STAGEB;
#pragma unroll
        for (int ks = 0; ks < 2; ks++) {
            uint32_t a[4][4], b[2][4];
#pragma unroll
            for (int mf = 0; mf < 4; mf++) ldsm4(a[mf], aAddr + so + mf*1280 + ks*32);
#pragma unroll
            for (int jp = 0; jp < 2; jp++) ldsm4(b[jp], bAddr + so + jp*1280 + ks*32);
#pragma unroll
            for (int mf = 0; mf < 4; mf++)
#pragma unroll
                for (int nf = 0; nf < 4; nf++)
                    mma16816(acc[mf][nf], a[mf], &b[nf >> 1][(nf & 1) * 2]);
        }
    }
#undef G_LOAD

    const int crow = lane >> 2, ccol = (lane & 3) * 2;
#pragma unroll
    for (int mf = 0; mf < 4; mf++) {
        const int row = m0 + wm*64 + mf*16 + crow;
#pragma unroll
        for (int nf = 0; nf < 4; nf++) {
            const int col = n0 + wn*32 + nf*8 + ccol;
            if (col < N) {
                float2 v0 = make_float2(acc[mf][nf][0], acc[mf][nf][1]);
                float2 v1 = make_float2(acc[mf][nf][2], acc[mf][nf][3]);
                *(float2*)&Cout[(size_t)row * N + col]       = v0;
                *(float2*)&Cout[(size_t)(row + 8) * N + col] = v1;
            }
        }
    }
}

// ======== bf16 splits (vectorized x4) ========
__device__ __forceinline__ void split3_act(__nv_bfloat16* dst, size_t rb, int K, int k, float v) {
    __nv_bfloat16 hi = __float2bfloat16(v);
    __nv_bfloat16 lo = __float2bfloat16(v - __bfloat162float(hi));
    dst[rb + k] = hi; dst[rb + K + k] = lo; dst[rb + 2*K + k] = hi;
}
__device__ __forceinline__ void store_hilo4(__nv_bfloat16* dst, size_t off_hi, size_t off_lo,
                                            float v0, float v1, float v2, float v3)
{
    __nv_bfloat16 h0 = __float2bfloat16(v0), h1 = __float2bfloat16(v1);
    __nv_bfloat16 h2 = __float2bfloat16(v2), h3 = __float2bfloat16(v3);
    __nv_bfloat16 l0 = __float2bfloat16(v0 - __bfloat162float(h0));
    __nv_bfloat16 l1 = __float2bfloat16(v1 - __bfloat162float(h1));
    __nv_bfloat16 l2 = __float2bfloat16(v2 - __bfloat162float(h2));
    __nv_bfloat16 l3 = __float2bfloat16(v3 - __bfloat162float(h3));
    *(__nv_bfloat162*)(dst + off_hi)     = __nv_bfloat162(h0, h1);
    *(__nv_bfloat162*)(dst + off_hi + 2) = __nv_bfloat162(h2, h3);
    *(__nv_bfloat162*)(dst + off_lo)     = __nv_bfloat162(l0, l1);
    *(__nv_bfloat162*)(dst + off_lo + 2) = __nv_bfloat162(l2, l3);
}

__global__ __launch_bounds__(256) void split_act(const float* __restrict__ src,
    __nv_bfloat16* __restrict__ dst, int rows, int K)
{
    int i = blockIdx.x * 256 + threadIdx.x;
    int kq = K >> 2;
    if (i >= rows * kq) return;
    int r = i / kq, k = (i - r * kq) * 4;
    float4 v = *(const float4*)(src + (size_t)r * K + k);
    size_t b = (size_t)r * 3 * K + k;
    store_hilo4(dst, b, b + K, v.x, v.y, v.z, v.w);
    __nv_bfloat162 h01 = __nv_bfloat162(__float2bfloat16(v.x), __float2bfloat16(v.y));
    __nv_bfloat162 h23 = __nv_bfloat162(__float2bfloat16(v.z), __float2bfloat16(v.w));
    *(__nv_bfloat162*)(dst + b + 2*K)     = h01;
    *(__nv_bfloat162*)(dst + b + 2*K + 2) = h23;
}

__global__ __launch_bounds__(256) void split_wt(const float* __restrict__ src,
    __nv_bfloat16* __restrict__ dst, int N, int Npad, int K)
{
    int i = blockIdx.x * 256 + threadIdx.x;
    int kq = K >> 2;
    if (i >= Npad * kq) return;
    int r = i / kq, k = (i - r * kq) * 4;
    float4 v;
    if (r < N) v = *(const float4*)(src + (size_t)r * K + k);
    else       v = make_float4(0.f, 0.f, 0.f, 0.f);
    size_t b = (size_t)r * 3 * K + k;
    store_hilo4(dst, b, b + 2*K, v.x, v.y, v.z, v.w);
    __nv_bfloat162 h01 = __nv_bfloat162(__float2bfloat16(v.x), __float2bfloat16(v.y));
    __nv_bfloat162 h23 = __nv_bfloat162(__float2bfloat16(v.z), __float2bfloat16(v.w));
    *(__nv_bfloat162*)(dst + b + K)     = h01;
    *(__nv_bfloat162*)(dst + b + K + 2) = h23;
}

// ======== Mamba pointwise ========
__global__ __launch_bounds__(256) void dt_kernel(const float* __restrict__ dt_bias, const float* __restrict__ A_log)
{
    int idx = blockIdx.x * 256 + threadIdx.x;
    int h = idx & 15, r = idx >> 4;
    float v = g_zx[(size_t)r * DPROJ + (DPROJ - NH) + h] + dt_bias[h];
    float dt = (v > 20.f) ? v : log1pf(expf(v));
    g_dt[idx] = dt;
    g_ldA[idx] = -dt * expf(A_log[h]);
}
__global__ __launch_bounds__(256) void conv_kernel(const float* __restrict__ cw, const float* __restrict__ cb)
{
    int idx = blockIdx.x * 256 + threadIdx.x;
    if (idx >= NROWS * CDIM) return;
    int c = idx % CDIM, r = idx / CDIM, l = r & (LL - 1);
    float acc = cb[c];
#pragma unroll
    for (int i = 0; i < 4; i++) {
        int li = l - 3 + i;
        if (li >= 0) acc += g_zx[(size_t)(r - 3 + i) * DPROJ + DI + c] * cw[c * 4 + i];
    }
    g_xbc[idx] = acc / (1.f + expf(-acc));
}

// ======== chunked scan ========
__device__ __forceinline__ float dot4f(float4 a, float4 b) { return a.x*b.x + a.y*b.y + a.z*b.z + a.w*b.w; }

__global__ __launch_bounds__(256) void scan_chunk(const float* __restrict__ Dv)
{
    extern __shared__ float sm[];
    float* sX  = sm;
    float* sB  = sm + 64*68;
    float* sCG = sm + 2*64*68;
    float* sdt = sm + 3*64*68;
    float* sL  = sdt + 64;
    float* sW  = sL + 64;
    const int bhc = blockIdx.x;
    const int bh = bhc >> 4, c = bhc & 15;
    const int b = bh >> 4, h = bh & 15;
    const int tid = threadIdx.x;
    const size_t row0 = (size_t)b * LL + c * 64;

    for (int i = tid; i < 64*64; i += 256) {
        int t = i >> 6, n = i & 63;
        size_t rb = (row0 + t) * CDIM;
        sX[t*68+n]  = g_xbc[rb + h*64 + n];
        sB[t*68+n]  = g_xbc[rb + DI + n];
        sCG[t*68+n] = g_xbc[rb + DI + DS + n];
    }
    if (tid < 64) {
        size_t rr = (row0 + tid) * NH + h;
        sdt[tid] = g_dt[rr]; sL[tid] = g_ldA[rr];
    }
    __syncthreads();
    if (tid == 0) { float a = 0.f; for (int t = 0; t < 64; t++) { a += sL[t]; sL[t] = a; } }
    __syncthreads();
    if (tid < 64) {
        sW[tid] = __expf(sL[63] - sL[tid]) * sdt[tid];
        g_cl[(size_t)bhc * 64 + tid] = sL[tid];
    }
    __syncthreads();

    const int ty = tid >> 4, tx = tid & 15;
    float acc[4][4];
#pragma unroll
    for (int i = 0; i < 4; i++)
#pragma unroll
        for (int j = 0; j < 4; j++) acc[i][j] = 0.f;
    for (int n = 0; n < 64; n += 4) {
        float4 cv[4], bv[4];
#pragma unroll
        for (int i = 0; i < 4; i++) cv[i] = *(const float4*)&sCG[(ty*4+i)*68 + n];
#pragma unroll
        for (int j = 0; j < 4; j++) bv[j] = *(const float4*)&sB[(tx*4+j)*68 + n];
#pragma unroll
        for (int i = 0; i < 4; i++)
#pragma unroll
            for (int j = 0; j < 4; j++) acc[i][j] += dot4f(cv[i], bv[j]);
    }
    __syncthreads();
#pragma unroll
    for (int i = 0; i < 4; i++) {
        int t = ty*4 + i; float lt = sL[t];
#pragma unroll
        for (int j = 0; j < 4; j++) {
            int tau = tx*4 + j;
            sCG[t*68+tau] = (tau <= t) ? __expf(lt - sL[tau]) * sdt[tau] * acc[i][j] : 0.f;
        }
    }
    __syncthreads();

    float acc2[4][4];
#pragma unroll
    for (int i = 0; i < 4; i++)
#pragma unroll
        for (int j = 0; j < 4; j++) acc2[i][j] = 0.f;
    for (int tau = 0; tau < 64; tau += 4) {
        float xr[4][4];
#pragma unroll
        for (int s = 0; s < 4; s++) *(float4*)xr[s] = *(const float4*)&sX[(tau+s)*68 + tx*4];
#pragma unroll
        for (int i = 0; i < 4; i++) {
            float gr[4];
            *(float4*)gr = *(const float4*)&sCG[(ty*4+i)*68 + tau];
#pragma unroll
            for (int j = 0; j < 4; j++)
                acc2[i][j] += gr[0]*xr[0][j] + gr[1]*xr[1][j] + gr[2]*xr[2][j] + gr[3]*xr[3][j];
        }
    }
    const float Dh = Dv[h];
#pragma unroll
    for (int i = 0; i < 4; i++) {
        int t = ty*4 + i;
#pragma unroll
        for (int j = 0; j < 4; j++) {
            int p = tx*4 + j;
            g_y[(row0 + t) * DI + h*64 + p] = acc2[i][j] + Dh * sX[t*68+p];
        }
    }

    float acc3[4][4];
#pragma unroll
    for (int i = 0; i < 4; i++)
#pragma unroll
        for (int j = 0; j < 4; j++) acc3[i][j] = 0.f;
    for (int tau = 0; tau < 64; tau++) {
        float w = sW[tau];
        float xp[4], bn[4];
        *(float4*)xp = *(const float4*)&sX[tau*68 + ty*4];
        *(float4*)bn = *(const float4*)&sB[tau*68 + tx*4];
#pragma unroll
        for (int i = 0; i < 4; i++) {
            float xw = w * xp[i];
#pragma unroll
            for (int j = 0; j < 4; j++) acc3[i][j] += xw * bn[j];
        }
    }
#pragma unroll
    for (int i = 0; i < 4; i++)
#pragma unroll
        for (int j = 0; j < 4; j++)
            g_S[(size_t)bhc * 4096 + (ty*4+i) * 64 + (tx*4+j)] = acc3[i][j];
}

__global__ __launch_bounds__(256) void scan_seq()
{
    const int bh = blockIdx.x;
    const int tid = threadIdx.x;
    float s[16];
#pragma unroll
    for (int i = 0; i < 16; i++) s[i] = 0.f;
    const size_t base = (size_t)bh * NCHUNK * 4096;
    for (int c = 0; c < NCHUNK; c++) {
        float P = __expf(g_cl[((size_t)bh * NCHUNK + c) * 64 + 63]);
        size_t off = base + (size_t)c * 4096 + (size_t)tid * 16;
#pragma unroll
        for (int i = 0; i < 16; i += 4) {
            float4 Sv = *(const float4*)&g_S[off + i];
            *(float4*)&g_Sin[off + i] = make_float4(s[i], s[i+1], s[i+2], s[i+3]);
            s[i]   = s[i]  *P + Sv.x; s[i+1] = s[i+1]*P + Sv.y;
            s[i+2] = s[i+2]*P + Sv.z; s[i+3] = s[i+3]*P + Sv.w;
        }
    }
}

__global__ __launch_bounds__(256) void scan_inter()
{
    __shared__ float sC[64*68];
    __shared__ float sS[64*68];
    __shared__ float sE[64];
    const int bhc = blockIdx.x;
    const int bh = bhc >> 4, c = bhc & 15;
    const int b = bh >> 4, h = bh & 15;
    const int tid = threadIdx.x;
    const size_t row0 = (size_t)b * LL + c * 64;

    for (int i = tid; i < 64*64; i += 256) {
        int t = i >> 6, n = i & 63;
        sC[t*68+n] = g_xbc[(row0 + t) * CDIM + DI + DS + n];
        sS[t*68+n] = g_Sin[(size_t)bhc * 4096 + t * 64 + n];
    }
    if (tid < 64) sE[tid] = __expf(g_cl[(size_t)bhc * 64 + tid]);
    __syncthreads();

    const int ty = tid >> 4, tx = tid & 15;
    float acc[4][4];
#pragma unroll
    for (int i = 0; i < 4; i++)
#pragma unroll
        for (int j = 0; j < 4; j++) acc[i][j] = 0.f;
    for (int n = 0; n < 64; n += 4) {
        float4 cv[4], sv[4];
#pragma unroll
        for (int i = 0; i < 4; i++) cv[i] = *(const float4*)&sC[(ty*4+i)*68 + n];
#pragma unroll
        for (int j = 0; j < 4; j++) sv[j] = *(const float4*)&sS[(tx*4+j)*68 + n];
#pragma unroll
        for (int i = 0; i < 4; i++)
#pragma unroll
            for (int j = 0; j < 4; j++) acc[i][j] += dot4f(cv[i], sv[j]);
    }
#pragma unroll
    for (int i = 0; i < 4; i++) {
        int t = ty*4 + i; float e = sE[t];
#pragma unroll
        for (int j = 0; j < 4; j++) {
            size_t ix = (row0 + t) * DI + h*64 + tx*4 + j;
            g_y[ix] += e * acc[i][j];
        }
    }
}

// ======== norms / gating / GLU ========
__device__ __forceinline__ float block_reduce_sum(float v, float* red)
{
#pragma unroll
    for (int o = 16; o; o >>= 1) v += __shfl_xor_sync(0xffffffffu, v, o);
    if ((threadIdx.x & 31) == 0) red[threadIdx.x >> 5] = v;
    __syncthreads();
    float t = 0.f;
#pragma unroll
    for (int i = 0; i < 8; i++) t += red[i];
    return t;
}

__global__ __launch_bounds__(256) void gate_norm_kernel(const float* __restrict__ norm_w)
{
    __shared__ float red[8];
    int r = blockIdx.x;
    const float* zrow = g_zx + (size_t)r * DPROJ;
    const float* yrow = g_y + (size_t)r * DI;
    float vals[4]; float ss = 0.f;
#pragma unroll
    for (int i = 0; i < 4; i++) {
        int c = threadIdx.x + i*256;
        float z = zrow[c];
        float g = yrow[c] * (z / (1.f + expf(-z)));
        vals[i] = g; ss += g*g;
    }
    float sc = rsqrtf(block_reduce_sum(ss, red) * (1.f/1024.f) + EPSV);
    size_t rb = (size_t)r * 3 * DI;
#pragma unroll
    for (int i = 0; i < 4; i++) {
        int c = threadIdx.x + i*256;
        split3_act(g_gnb, rb, DI, c, vals[i] * sc * norm_w[c]);
    }
}

// reads split-K partials g_mo + g_mo2
__global__ __launch_bounds__(256) void add_rms_hT_kernel(const float* __restrict__ u)
{
    __shared__ float red[8];
    int r = blockIdx.x;
    int b = r >> 10, l = r & (LL - 1);
    const float* ur = u + (size_t)r * DM;
    const float* mr = g_mo + (size_t)r * DM;
    const float* m2r = g_mo2 + (size_t)r * DM;
    float vals[2]; float ss = 0.f;
#pragma unroll
    for (int i = 0; i < 2; i++) {
        int d = threadIdx.x + i*256;
        float v = ur[d] + (mr[d] + m2r[d]);
        vals[i] = v; ss += v*v;
    }
    float sc = rsqrtf(block_reduce_sum(ss, red) * (1.f/512.f) + EPSV);
#pragma unroll
    for (int i = 0; i < 2; i++) {
        int d = threadIdx.x + i*256;
        g_hT[(size_t)(b*DM + d) * LL + l] = vals[i] * sc;
    }
}

__global__ __launch_bounds__(256) void glu_kernel(const float* __restrict__ t,
    __nv_bfloat16* __restrict__ o, int half, int total4)
{
    int i = blockIdx.x * 256 + threadIdx.x;
    if (i >= total4) return;
    int hq = half >> 2;
    int r = i / hq, j = (i - r * hq) * 4;
    const float* row = t + (size_t)r * 2 * half;
    float4 gv = *(const float4*)(row + j);
    float4 uv = *(const float4*)(row + half + j);
    float v0 = (gv.x / (1.f + expf(-gv.x))) * uv.x;
    float v1 = (gv.y / (1.f + expf(-gv.y))) * uv.y;
    float v2 = (gv.z / (1.f + expf(-gv.z))) * uv.z;
    float v3 = (gv.w / (1.f + expf(-gv.w))) * uv.w;
    size_t b = (size_t)r * 3 * half + j;
    store_hilo4(o, b, b + half, v0, v1, v2, v3);
    __nv_bfloat162 h01 = __nv_bfloat162(__float2bfloat16(v0), __float2bfloat16(v1));
    __nv_bfloat162 h23 = __nv_bfloat162(__float2bfloat16(v2), __float2bfloat16(v3));
    *(__nv_bfloat162*)(o + b + 2*half)     = h01;
    *(__nv_bfloat162*)(o + b + 2*half + 2) = h23;
}

// reads split-K partials g_t2 + g_t22
__global__ __launch_bounds__(256) void add_rms_x2_kernel()
{
    __shared__ float red[8];
    int r = blockIdx.x;
    int b = r >> 9, d = r & (DM - 1);
    const float* hr = g_hT + (size_t)r * LL;
    const float* tr = g_t2 + (size_t)r * LL;
    const float* t2r = g_t22 + (size_t)r * LL;
    float vals[4]; float ss = 0.f;
#pragma unroll
    for (int i = 0; i < 4; i++) {
        int l = threadIdx.x + i*256;
        float v = hr[l] + (tr[l] + t2r[l]);
        vals[i] = v; ss += v*v;
    }
    float sc = rsqrtf(block_reduce_sum(ss, red) * (1.f/1024.f) + EPSV);
#pragma unroll
    for (int i = 0; i < 4; i++) {
        int l = threadIdx.x + i*256;
        g_h2[(size_t)(b*LL + l) * DM + d] = vals[i] * sc;
    }
}

// reads split-K partials g_m2 + g_m22
__global__ __launch_bounds__(256) void final_rms_kernel(float* __restrict__ out)
{
    __shared__ float red[8];
    int r = blockIdx.x;
    const float* hr = g_h2 + (size_t)r * DM;
    const float* mr = g_m2 + (size_t)r * DM;
    const float* m2r = g_m22 + (size_t)r * DM;
    float vals[2]; float ss = 0.f;
#pragma unroll
    for (int i = 0; i < 2; i++) {
        int d = threadIdx.x + i*256;
        float v = hr[d] + (mr[d] + m2r[d]);
        vals[i] = v; ss += v*v;
    }
    float sc = rsqrtf(block_reduce_sum(ss, red) * (1.f/512.f) + EPSV);
#pragma unroll
    for (int i = 0; i < 2; i++) {
        int d = threadIdx.x + i*256;
        out[(size_t)r * DM + d] = vals[i] * sc;
    }
}

// ======== launch ========
#define GETSYM(p, s) cudaGetSymbolAddress((void**)&p, s)
extern "C" void kernel_launch(void* const* d_in, const int* in_sizes, int n_in,
                              void* d_out, int out_size)
{
    const float* u          = (const float*)d_in[0];
    const float* in_proj_w  = (const float*)d_in[1];
    const float* conv_w     = (const float*)d_in[2];
    const float* conv_b     = (const float*)d_in[3];
    const float* dt_bias    = (const float*)d_in[4];
    const float* A_log      = (const float*)d_in[5];
    const float* Dv         = (const float*)d_in[6];
    const float* norm_w     = (const float*)d_in[7];
    const float* out_proj_w = (const float*)d_in[8];
    const float* gu_t       = (const float*)d_in[9];
    const float* down_t     = (const float*)d_in[10];
    const float* gu_m       = (const float*)d_in[11];
    const float* down_m     = (const float*)d_in[12];
    float* out = (float*)d_out;

    float *zx, *mo, *mo2, *hT, *t1, *t2, *t22, *h2, *m1, *m2, *m22;
    __nv_bfloat16 *ub, *gnb, *hTb, *tactb, *h2b, *mactb, *wip, *wop, *wgt, *wdt, *wgm, *wdm;
    GETSYM(zx, g_zx); GETSYM(mo, g_mo); GETSYM(mo2, g_mo2); GETSYM(hT, g_hT);
    GETSYM(t1, g_t1); GETSYM(t2, g_t2); GETSYM(t22, g_t22);
    GETSYM(h2, g_h2); GETSYM(m1, g_m1); GETSYM(m2, g_m2); GETSYM(m22, g_m22);
    GETSYM(ub, g_ub); GETSYM(gnb, g_gnb); GETSYM(hTb, g_hTb); GETSYM(tactb, g_tactb);
    GETSYM(h2b, g_h2b); GETSYM(mactb, g_mactb);
    GETSYM(wip, g_wip); GETSYM(wop, g_wop); GETSYM(wgt, g_wgt);
    GETSYM(wdt, g_wdt); GETSYM(wgm, g_wgm); GETSYM(wdm, g_wdm);

    cudaFuncSetAttribute(scan_chunk, cudaFuncAttributeMaxDynamicSharedMemorySize, 53248);
    cudaFuncSetAttribute(gemm_tc, cudaFuncAttributeMaxDynamicSharedMemorySize, G_SMEM);

    // weight + input splits (bf16 hi/lo, K'=3K), vectorized x4
    split_wt<<<(2304*(512/4) + 255)/256, 256>>>(in_proj_w, wip, DPROJ, 2304, DM);
    split_wt<<<(512*(1024/4) + 255)/256, 256>>>(out_proj_w, wop, DM, DM, DI);
    split_wt<<<(5632*(1024/4) + 255)/256, 256>>>(gu_t, wgt, 2*IT, 2*IT, LL);
    split_wt<<<(1024*(2816/4) + 255)/256, 256>>>(down_t, wdt, LL, LL, IT);
    split_wt<<<(3072*(512/4) + 255)/256, 256>>>(gu_m, wgm, 2*IM, 2*IM, DM);
    split_wt<<<(512*(1536/4) + 255)/256, 256>>>(down_m, wdm, DM, DM, IM);
    split_act<<<(NROWS*(DM/4) + 255)/256, 256>>>(u, ub, NROWS, DM);

    // ---- Mamba2 ----
    gemm_tc<<<dim3(18, 32, 1), 256, G_SMEM>>>(ub, wip, zx, zx, NROWS, DPROJ, 3*DM);
    dt_kernel<<<(NROWS*NH)/256, 256>>>(dt_bias, A_log);
    conv_kernel<<<(NROWS*CDIM + 255)/256, 256>>>(conv_w, conv_b);
    scan_chunk<<<BB*NH*NCHUNK, 256, 52992>>>(Dv);
    scan_seq<<<BB*NH, 256>>>();
    scan_inter<<<BB*NH*NCHUNK, 256>>>();
    gate_norm_kernel<<<NROWS, 256>>>(norm_w);
    gemm_tc<<<dim3(4, 32, 2), 256, G_SMEM>>>(gnb, wop, mo, mo2, NROWS, DM, 3*DI);       // split-K
    add_rms_hT_kernel<<<NROWS, 256>>>(u);
    split_act<<<(TROWS*(LL/4) + 255)/256, 256>>>(hT, hTb, TROWS, LL);

    // ---- token-mixing SwiGLU ----
    gemm_tc<<<dim3(44, 16, 1), 256, G_SMEM>>>(hTb, wgt, t1, t1, TROWS, 2*IT, 3*LL);
    glu_kernel<<<(TROWS*(IT/4) + 255)/256, 256>>>(t1, tactb, IT, TROWS*(IT/4));
    gemm_tc<<<dim3(8, 16, 2), 256, G_SMEM>>>(tactb, wdt, t2, t22, TROWS, LL, 3*IT);     // split-K
    add_rms_x2_kernel<<<TROWS, 256>>>();
    split_act<<<(NROWS*(DM/4) + 255)/256, 256>>>(h2, h2b, NROWS, DM);

    // ---- channel SwiGLU ----
    gemm_tc<<<dim3(24, 32, 1), 256, G_SMEM>>>(h2b, wgm, m1, m1, NROWS, 2*IM, 3*DM);
    glu_kernel<<<(NROWS*(IM/4) + 255)/256, 256>>>(m1, mactb, IM, NROWS*(IM/4));
    gemm_tc<<<dim3(4, 32, 2), 256, G_SMEM>>>(mactb, wdm, m2, m22, NROWS, DM, 3*IM);     // split-K
    final_rms_kernel<<<NROWS, 256>>>(out);
}